// round 2
// baseline (speedup 1.0000x reference)
#include <cuda_runtime.h>
#include <cuda_bf16.h>

// Problem constants: B=8, C=64, H=W=256
#define NB 8
#define NC 64
#define NP 65536              // H*W
#define HW 256                // H (== W)
#define CW 16384              // C*W
#define C2ELEMS (NB*NC*NP)    // 33554432
#define SELEMS  (NB*HW*HW)    // 524288
#define EPSBN 1e-5f
#define SLOPE 0.2f

// ---------------- scratch (device globals; no allocation allowed) -------------
__device__ float g_w1f[NC];
__device__ float g_b1f;
__device__ float g_wAfT[NC*NC];   // transposed [k][o]
__device__ float g_bAf[NC];
__device__ float g_wOfT[NC*NC];   // transposed [k][o]
__device__ float g_bOf[NC];
__device__ float g_C1[NB*NP];                 // (B,H,W)  2MB
__device__ float g_C2[C2ELEMS];               // (B,C,H,W) 134MB
__device__ float g_G[2*NB*HW*HW];             // gram matrices, 4MB
__device__ float g_S12[NB*HW*HW];             // S1+S2, 2MB
__device__ float g_M[C2ELEMS];                // (S1+S2)@C2view, 134MB

__device__ __forceinline__ float lrelu(float y) { return y >= 0.f ? y : SLOPE * y; }

// ---------------- K0: fold BN into conv weights -------------------------------
__global__ void k0_fold(const float* __restrict__ w1, const float* __restrict__ b1,
                        const float* __restrict__ g1, const float* __restrict__ be1,
                        const float* __restrict__ m1, const float* __restrict__ v1,
                        const float* __restrict__ wA, const float* __restrict__ bA,
                        const float* __restrict__ gA, const float* __restrict__ beA,
                        const float* __restrict__ mA, const float* __restrict__ vA,
                        const float* __restrict__ wO, const float* __restrict__ bO,
                        const float* __restrict__ gO, const float* __restrict__ beO,
                        const float* __restrict__ mO, const float* __restrict__ vO) {
    int o = threadIdx.x;  // 0..63
    float aA = gA[o] * rsqrtf(vA[o] + EPSBN);
    float aO = gO[o] * rsqrtf(vO[o] + EPSBN);
    for (int c = 0; c < NC; c++) {
        g_wAfT[c*NC + o] = aA * wA[o*NC + c];
        g_wOfT[c*NC + o] = aO * wO[o*NC + c];
    }
    g_bAf[o] = aA * (bA[o] - mA[o]) + beA[o];
    g_bOf[o] = aO * (bO[o] - mO[o]) + beO[o];
    float a1 = g1[0] * rsqrtf(v1[0] + EPSBN);
    g_w1f[o] = a1 * w1[o];
    if (o == 0) g_b1f = a1 * (b1[0] - m1[0]) + be1[0];
}

// ---------------- K1: fused C1 (C->1) and C2 (C->C) over one pass of x --------
// grid (NP/128, NB), 256 threads. smem: wT 16KB + xs 32KB.
__global__ __launch_bounds__(256) void k1_c1c2(const float* __restrict__ x) {
    __shared__ float wT[NC*NC];     // [k][o]
    __shared__ float xs[NC*128];    // [c][p]
    int b = blockIdx.y;
    int p0 = blockIdx.x * 128;
    int tid = threadIdx.x;

    for (int i = tid; i < NC*NC; i += 256) wT[i] = g_wAfT[i];

    const float* xb = x + (size_t)b * NC * NP;
    float4* xs4 = (float4*)xs;
    for (int i = tid; i < NC*32; i += 256) {
        int c = i >> 5, pq = i & 31;
        xs4[i] = ((const float4*)(xb + (size_t)c*NP + p0))[pq];
    }
    __syncthreads();

    // C1 for these 128 pixels
    if (tid < 128) {
        float s = 0.f;
        #pragma unroll
        for (int c = 0; c < NC; c++) s += g_w1f[c] * xs[c*128 + tid];
        s += g_b1f;
        g_C1[(size_t)b*NP + p0 + tid] = lrelu(s);
    }

    // C2: thread computes 4 channels x 8 pixels
    int og = tid >> 4, pg = tid & 15;
    float acc[4][8];
    #pragma unroll
    for (int r = 0; r < 4; r++)
        #pragma unroll
        for (int p = 0; p < 8; p++) acc[r][p] = 0.f;

    #pragma unroll 8
    for (int k = 0; k < NC; k++) {
        float4 a = *(float4*)&wT[k*NC + og*4];
        float4 b0 = *(float4*)&xs[k*128 + pg*8];
        float4 b1v = *(float4*)&xs[k*128 + pg*8 + 4];
        float av[4] = {a.x, a.y, a.z, a.w};
        float bv[8] = {b0.x, b0.y, b0.z, b0.w, b1v.x, b1v.y, b1v.z, b1v.w};
        #pragma unroll
        for (int r = 0; r < 4; r++)
            #pragma unroll
            for (int p = 0; p < 8; p++) acc[r][p] = fmaf(av[r], bv[p], acc[r][p]);
    }

    #pragma unroll
    for (int r = 0; r < 4; r++) {
        int o = og*4 + r;
        float bo = g_bAf[o];
        float4 y0, y1;
        y0.x = lrelu(acc[r][0]+bo); y0.y = lrelu(acc[r][1]+bo);
        y0.z = lrelu(acc[r][2]+bo); y0.w = lrelu(acc[r][3]+bo);
        y1.x = lrelu(acc[r][4]+bo); y1.y = lrelu(acc[r][5]+bo);
        y1.z = lrelu(acc[r][6]+bo); y1.w = lrelu(acc[r][7]+bo);
        float* dst = &g_C2[(size_t)b*NC*NP + (size_t)o*NP + p0 + pg*8];
        *(float4*)dst = y0;
        *(float4*)(dst+4) = y1;
    }
}

// ---------------- K2a: Gram matrices G1 = C1 C1^T, G2 = C1^T C1 ---------------
// grid (4,4,16) where z = b*2+mat; 64x64 tile, Kc=32, 256 thr, 4x4 micro.
__global__ __launch_bounds__(256) void k2a_gram() {
    int mat = blockIdx.z & 1;
    int b = blockIdx.z >> 1;
    int j0 = blockIdx.x * 64;
    int i0 = blockIdx.y * 64;
    __shared__ float As[32][64];
    __shared__ float Bs[32][64];
    const float* A = g_C1 + (size_t)b * NP;
    int tid = threadIdx.x;
    int ti = tid >> 4, tj = tid & 15;
    float acc[4][4];
    #pragma unroll
    for (int r = 0; r < 4; r++)
        #pragma unroll
        for (int c = 0; c < 4; c++) acc[r][c] = 0.f;

    for (int k0 = 0; k0 < HW; k0 += 32) {
        if (mat == 0) {  // G1[i,j] = sum_k C1[i,k] C1[j,k] : rows, transpose into smem
            int i = tid >> 2;          // 0..63
            int kq = (tid & 3) * 8;    // 0,8,16,24
            float4 va0 = *(const float4*)&A[(i0+i)*HW + k0 + kq];
            float4 va1 = *(const float4*)&A[(i0+i)*HW + k0 + kq + 4];
            As[kq+0][i]=va0.x; As[kq+1][i]=va0.y; As[kq+2][i]=va0.z; As[kq+3][i]=va0.w;
            As[kq+4][i]=va1.x; As[kq+5][i]=va1.y; As[kq+6][i]=va1.z; As[kq+7][i]=va1.w;
            float4 vb0 = *(const float4*)&A[(j0+i)*HW + k0 + kq];
            float4 vb1 = *(const float4*)&A[(j0+i)*HW + k0 + kq + 4];
            Bs[kq+0][i]=vb0.x; Bs[kq+1][i]=vb0.y; Bs[kq+2][i]=vb0.z; Bs[kq+3][i]=vb0.w;
            Bs[kq+4][i]=vb1.x; Bs[kq+5][i]=vb1.y; Bs[kq+6][i]=vb1.z; Bs[kq+7][i]=vb1.w;
        } else {         // G2[i,j] = sum_k C1[k,i] C1[k,j] : columns, direct copy
            int k = tid >> 3, iq = (tid & 7) * 8;
            *(float4*)&As[k][iq]   = *(const float4*)&A[(k0+k)*HW + i0 + iq];
            *(float4*)&As[k][iq+4] = *(const float4*)&A[(k0+k)*HW + i0 + iq + 4];
            *(float4*)&Bs[k][iq]   = *(const float4*)&A[(k0+k)*HW + j0 + iq];
            *(float4*)&Bs[k][iq+4] = *(const float4*)&A[(k0+k)*HW + j0 + iq + 4];
        }
        __syncthreads();
        #pragma unroll
        for (int kk = 0; kk < 32; kk++) {
            float4 a4 = *(float4*)&As[kk][ti*4];
            float4 b4 = *(float4*)&Bs[kk][tj*4];
            float av[4] = {a4.x,a4.y,a4.z,a4.w};
            float bv[4] = {b4.x,b4.y,b4.z,b4.w};
            #pragma unroll
            for (int r = 0; r < 4; r++)
                #pragma unroll
                for (int c = 0; c < 4; c++) acc[r][c] = fmaf(av[r], bv[c], acc[r][c]);
        }
        __syncthreads();
    }
    float* G = g_G + ((size_t)(mat*NB + b)) * HW * HW;
    #pragma unroll
    for (int r = 0; r < 4; r++) {
        float4 v; v.x=acc[r][0]; v.y=acc[r][1]; v.z=acc[r][2]; v.w=acc[r][3];
        *(float4*)&G[(i0 + ti*4 + r)*HW + j0 + tj*4] = v;
    }
}

// ---------------- K2b: row softmax of G1,G2 -> S1,S2 (output) and S12 ---------
// grid (256, NB), 256 threads: one row, one element per thread.
__global__ __launch_bounds__(256) void k2b_softmax(float* __restrict__ S1o,
                                                   float* __restrict__ S2o) {
    int i = blockIdx.x, b = blockIdx.y, tid = threadIdx.x;
    __shared__ float red[8];
    __shared__ float bc;
    float rr[2];
    #pragma unroll
    for (int mat = 0; mat < 2; mat++) {
        float v = g_G[(((size_t)(mat*NB + b))*HW + i)*HW + tid];
        // max reduce
        float m = v;
        #pragma unroll
        for (int o = 16; o; o >>= 1) m = fmaxf(m, __shfl_xor_sync(0xffffffffu, m, o));
        if ((tid & 31) == 0) red[tid >> 5] = m;
        __syncthreads();
        if (tid == 0) {
            float t = red[0];
            #pragma unroll
            for (int j = 1; j < 8; j++) t = fmaxf(t, red[j]);
            bc = t;
        }
        __syncthreads();
        float e = expf(v - bc);
        float s = e;
        #pragma unroll
        for (int o = 16; o; o >>= 1) s += __shfl_xor_sync(0xffffffffu, s, o);
        if ((tid & 31) == 0) red[tid >> 5] = s;
        __syncthreads();
        if (tid == 0) {
            float t = 0.f;
            #pragma unroll
            for (int j = 0; j < 8; j++) t += red[j];
            bc = t;
        }
        __syncthreads();
        rr[mat] = e / bc;
        float* dst = mat == 0 ? S1o : S2o;
        dst[((size_t)b*HW + i)*HW + tid] = rr[mat];
        __syncthreads();  // protect red/bc reuse
    }
    g_S12[((size_t)b*HW + i)*HW + tid] = rr[0] + rr[1];
}

// ---------------- K3: batched GEMM M = S12 @ C2view ----------------------------
// Per batch: A (256x256) @ B (256x16384). Tile 64(M) x 128(N), K chunks of 16.
// grid (128, 4, 8), 256 threads, 8x4 micro.
__global__ __launch_bounds__(256) void k3_bgemm() {
    int b = blockIdx.z;
    int m0 = blockIdx.y * 64;
    int n0 = blockIdx.x * 128;
    __shared__ float As[16][64];    // [k][m]
    __shared__ float Bs[16][128];   // [k][n]
    const float* A = g_S12 + (size_t)b * HW * HW;
    const float* Bm = g_C2 + (size_t)b * NC * NP;
    int tid = threadIdx.x;
    int ty = tid >> 5;  // 0..7  -> rows m0+ty*8+{0..7}
    int tx = tid & 31;  // 0..31 -> cols n0+tx*4+{0..3}

    float acc[8][4];
    #pragma unroll
    for (int r = 0; r < 8; r++)
        #pragma unroll
        for (int c = 0; c < 4; c++) acc[r][c] = 0.f;

    for (int k0 = 0; k0 < HW; k0 += 16) {
        {   // load A tile 64x16 (transpose in regs)
            int m = tid >> 2, kq = (tid & 3) * 4;
            float4 va = *(const float4*)&A[(m0+m)*HW + k0 + kq];
            As[kq+0][m]=va.x; As[kq+1][m]=va.y; As[kq+2][m]=va.z; As[kq+3][m]=va.w;
        }
        {   // load B tile 16x128
            int kk = tid >> 4, nq = (tid & 15) * 8;
            *(float4*)&Bs[kk][nq]   = *(const float4*)&Bm[(size_t)(k0+kk)*CW + n0 + nq];
            *(float4*)&Bs[kk][nq+4] = *(const float4*)&Bm[(size_t)(k0+kk)*CW + n0 + nq + 4];
        }
        __syncthreads();
        #pragma unroll
        for (int kk = 0; kk < 16; kk++) {
            float4 a0 = *(float4*)&As[kk][ty*8];
            float4 a1 = *(float4*)&As[kk][ty*8+4];
            float4 bb = *(float4*)&Bs[kk][tx*4];
            float av[8] = {a0.x,a0.y,a0.z,a0.w,a1.x,a1.y,a1.z,a1.w};
            float bv[4] = {bb.x,bb.y,bb.z,bb.w};
            #pragma unroll
            for (int r = 0; r < 8; r++)
                #pragma unroll
                for (int c = 0; c < 4; c++) acc[r][c] = fmaf(av[r], bv[c], acc[r][c]);
        }
        __syncthreads();
    }
    float* M = g_M + (size_t)b * NC * NP;
    #pragma unroll
    for (int r = 0; r < 8; r++) {
        float4 v; v.x=acc[r][0]; v.y=acc[r][1]; v.z=acc[r][2]; v.w=acc[r][3];
        *(float4*)&M[(size_t)(m0 + ty*8 + r)*CW + n0 + tx*4] = v;
    }
}

// ---------------- K4: C3 = lrelu(fold(M . wO)); out = C2 + C3 ------------------
// grid (NP/128, NB), 256 threads.
__global__ __launch_bounds__(256) void k4_out(float* __restrict__ out) {
    __shared__ float wT[NC*NC];
    __shared__ float xs[NC*128];
    int b = blockIdx.y;
    int p0 = blockIdx.x * 128;
    int tid = threadIdx.x;

    for (int i = tid; i < NC*NC; i += 256) wT[i] = g_wOfT[i];

    const float* mb = g_M + (size_t)b * NC * NP;
    float4* xs4 = (float4*)xs;
    for (int i = tid; i < NC*32; i += 256) {
        int c = i >> 5, pq = i & 31;
        xs4[i] = ((const float4*)(mb + (size_t)c*NP + p0))[pq];
    }
    __syncthreads();

    int og = tid >> 4, pg = tid & 15;
    float acc[4][8];
    #pragma unroll
    for (int r = 0; r < 4; r++)
        #pragma unroll
        for (int p = 0; p < 8; p++) acc[r][p] = 0.f;

    #pragma unroll 8
    for (int k = 0; k < NC; k++) {
        float4 a = *(float4*)&wT[k*NC + og*4];
        float4 b0 = *(float4*)&xs[k*128 + pg*8];
        float4 b1v = *(float4*)&xs[k*128 + pg*8 + 4];
        float av[4] = {a.x, a.y, a.z, a.w};
        float bv[8] = {b0.x, b0.y, b0.z, b0.w, b1v.x, b1v.y, b1v.z, b1v.w};
        #pragma unroll
        for (int r = 0; r < 4; r++)
            #pragma unroll
            for (int p = 0; p < 8; p++) acc[r][p] = fmaf(av[r], bv[p], acc[r][p]);
    }

    #pragma unroll
    for (int r = 0; r < 4; r++) {
        int o = og*4 + r;
        float bo = g_bOf[o];
        const float* c2p = &g_C2[(size_t)b*NC*NP + (size_t)o*NP + p0 + pg*8];
        float4 c20 = *(const float4*)c2p;
        float4 c21 = *(const float4*)(c2p + 4);
        float4 y0, y1;
        y0.x = c20.x + lrelu(acc[r][0]+bo); y0.y = c20.y + lrelu(acc[r][1]+bo);
        y0.z = c20.z + lrelu(acc[r][2]+bo); y0.w = c20.w + lrelu(acc[r][3]+bo);
        y1.x = c21.x + lrelu(acc[r][4]+bo); y1.y = c21.y + lrelu(acc[r][5]+bo);
        y1.z = c21.z + lrelu(acc[r][6]+bo); y1.w = c21.w + lrelu(acc[r][7]+bo);
        float* dst = &out[(size_t)b*NC*NP + (size_t)o*NP + p0 + pg*8];
        *(float4*)dst = y0;
        *(float4*)(dst+4) = y1;
    }
}

// ---------------- launch --------------------------------------------------------
extern "C" void kernel_launch(void* const* d_in, const int* in_sizes, int n_in,
                              void* d_out, int out_size) {
    const float* x   = (const float*)d_in[0];
    const float* w1  = (const float*)d_in[1];
    const float* b1  = (const float*)d_in[2];
    const float* g1  = (const float*)d_in[3];
    const float* be1 = (const float*)d_in[4];
    const float* m1  = (const float*)d_in[5];
    const float* v1  = (const float*)d_in[6];
    const float* wA  = (const float*)d_in[7];
    const float* bA  = (const float*)d_in[8];
    const float* gA  = (const float*)d_in[9];
    const float* beA = (const float*)d_in[10];
    const float* mA  = (const float*)d_in[11];
    const float* vA  = (const float*)d_in[12];
    const float* wO  = (const float*)d_in[13];
    const float* bO  = (const float*)d_in[14];
    const float* gO  = (const float*)d_in[15];
    const float* beO = (const float*)d_in[16];
    const float* mO  = (const float*)d_in[17];
    const float* vO  = (const float*)d_in[18];

    float* out = (float*)d_out;
    float* S1o = out + (size_t)C2ELEMS;
    float* S2o = S1o + (size_t)SELEMS;

    k0_fold<<<1, 64>>>(w1,b1,g1,be1,m1,v1, wA,bA,gA,beA,mA,vA, wO,bO,gO,beO,mO,vO);
    k1_c1c2<<<dim3(NP/128, NB), 256>>>(x);
    k2a_gram<<<dim3(4, 4, 2*NB), 256>>>();
    k2b_softmax<<<dim3(HW, NB), 256>>>(S1o, S2o);
    k3_bgemm<<<dim3(CW/128, HW/64, NB), 256>>>();
    k4_out<<<dim3(NP/128, NB), 256>>>(out);
}

// round 5
// speedup vs baseline: 1.4855x; 1.4855x over previous
#include <cuda_runtime.h>
#include <cuda_bf16.h>
#include <cstdint>

// Problem constants: B=8, C=64, H=W=256
#define NB 8
#define NC 64
#define NP 65536              // H*W
#define HW 256                // H (== W)
#define CW 16384              // C*W
#define C2ELEMS (NB*NC*NP)    // 33554432
#define SELEMS  (NB*HW*HW)    // 524288
#define EPSBN 1e-5f
#define SLOPE 0.2f

// ---------------- scratch (device globals; no allocation allowed) -------------
__device__ float g_w1f[NC];
__device__ float g_b1f;
__device__ float g_wAfT[NC*NC];   // transposed [k][o]
__device__ float g_bAf[NC];
__device__ float g_wOfT[NC*NC];   // transposed [k][o]
__device__ float g_bOf[NC];
__device__ float g_C1[NB*NP];                 // (B,H,W)  2MB
__device__ float g_C2[C2ELEMS];               // (B,C,H,W) fp32 exact (k4 residual)
__device__ float g_C2t[C2ELEMS];              // tf32-rounded copy for tensor GEMM
__device__ float g_G[2*NB*HW*HW];             // gram matrices, 4MB
__device__ float g_S12[SELEMS];               // S1+S2, tf32-rounded, 2MB
__device__ float g_M[C2ELEMS];                // (S1+S2)@C2view, 134MB

__device__ __forceinline__ float lrelu(float y) { return y >= 0.f ? y : SLOPE * y; }

__device__ __forceinline__ float to_tf32(float x) {
    uint32_t r;
    asm("cvt.rna.tf32.f32 %0, %1;" : "=r"(r) : "f"(x));
    return __uint_as_float(r);
}

// ---------------- K0: fold BN into conv weights -------------------------------
__global__ void k0_fold(const float* __restrict__ w1, const float* __restrict__ b1,
                        const float* __restrict__ g1, const float* __restrict__ be1,
                        const float* __restrict__ m1, const float* __restrict__ v1,
                        const float* __restrict__ wA, const float* __restrict__ bA,
                        const float* __restrict__ gA, const float* __restrict__ beA,
                        const float* __restrict__ mA, const float* __restrict__ vA,
                        const float* __restrict__ wO, const float* __restrict__ bO,
                        const float* __restrict__ gO, const float* __restrict__ beO,
                        const float* __restrict__ mO, const float* __restrict__ vO) {
    int o = threadIdx.x;  // 0..63
    float aA = gA[o] * rsqrtf(vA[o] + EPSBN);
    float aO = gO[o] * rsqrtf(vO[o] + EPSBN);
    for (int c = 0; c < NC; c++) {
        g_wAfT[c*NC + o] = aA * wA[o*NC + c];
        g_wOfT[c*NC + o] = aO * wO[o*NC + c];
    }
    g_bAf[o] = aA * (bA[o] - mA[o]) + beA[o];
    g_bOf[o] = aO * (bO[o] - mO[o]) + beO[o];
    float a1 = g1[0] * rsqrtf(v1[0] + EPSBN);
    g_w1f[o] = a1 * w1[o];
    if (o == 0) g_b1f = a1 * (b1[0] - m1[0]) + be1[0];
}

// ---------------- K1: fused C1 (C->1) and C2 (C->C) over one pass of x --------
__global__ __launch_bounds__(256) void k1_c1c2(const float* __restrict__ x) {
    __shared__ float wT[NC*NC];     // [k][o]
    __shared__ float xs[NC*128];    // [c][p]
    int b = blockIdx.y;
    int p0 = blockIdx.x * 128;
    int tid = threadIdx.x;

    for (int i = tid; i < NC*NC; i += 256) wT[i] = g_wAfT[i];

    const float* xb = x + (size_t)b * NC * NP;
    float4* xs4 = (float4*)xs;
    for (int i = tid; i < NC*32; i += 256) {
        int c = i >> 5, pq = i & 31;
        xs4[i] = ((const float4*)(xb + (size_t)c*NP + p0))[pq];
    }
    __syncthreads();

    // C1 for these 128 pixels
    if (tid < 128) {
        float s = 0.f;
        #pragma unroll
        for (int c = 0; c < NC; c++) s += g_w1f[c] * xs[c*128 + tid];
        s += g_b1f;
        g_C1[(size_t)b*NP + p0 + tid] = lrelu(s);
    }

    // C2: thread computes 4 channels x 8 pixels
    int og = tid >> 4, pg = tid & 15;
    float acc[4][8];
    #pragma unroll
    for (int r = 0; r < 4; r++)
        #pragma unroll
        for (int p = 0; p < 8; p++) acc[r][p] = 0.f;

    #pragma unroll 8
    for (int k = 0; k < NC; k++) {
        float4 a = *(float4*)&wT[k*NC + og*4];
        float4 b0 = *(float4*)&xs[k*128 + pg*8];
        float4 b1v = *(float4*)&xs[k*128 + pg*8 + 4];
        float av[4] = {a.x, a.y, a.z, a.w};
        float bv[8] = {b0.x, b0.y, b0.z, b0.w, b1v.x, b1v.y, b1v.z, b1v.w};
        #pragma unroll
        for (int r = 0; r < 4; r++)
            #pragma unroll
            for (int p = 0; p < 8; p++) acc[r][p] = fmaf(av[r], bv[p], acc[r][p]);
    }

    #pragma unroll
    for (int r = 0; r < 4; r++) {
        int o = og*4 + r;
        float bo = g_bAf[o];
        float4 y0, y1;
        y0.x = lrelu(acc[r][0]+bo); y0.y = lrelu(acc[r][1]+bo);
        y0.z = lrelu(acc[r][2]+bo); y0.w = lrelu(acc[r][3]+bo);
        y1.x = lrelu(acc[r][4]+bo); y1.y = lrelu(acc[r][5]+bo);
        y1.z = lrelu(acc[r][6]+bo); y1.w = lrelu(acc[r][7]+bo);
        size_t off = (size_t)b*NC*NP + (size_t)o*NP + p0 + pg*8;
        *(float4*)&g_C2[off] = y0;
        *(float4*)&g_C2[off+4] = y1;
        float4 t0, t1;
        t0.x = to_tf32(y0.x); t0.y = to_tf32(y0.y); t0.z = to_tf32(y0.z); t0.w = to_tf32(y0.w);
        t1.x = to_tf32(y1.x); t1.y = to_tf32(y1.y); t1.z = to_tf32(y1.z); t1.w = to_tf32(y1.w);
        *(float4*)&g_C2t[off] = t0;
        *(float4*)&g_C2t[off+4] = t1;
    }
}

// ---------------- K2a: Gram matrices G1 = C1 C1^T, G2 = C1^T C1 ---------------
__global__ __launch_bounds__(256) void k2a_gram() {
    int mat = blockIdx.z & 1;
    int b = blockIdx.z >> 1;
    int j0 = blockIdx.x * 64;
    int i0 = blockIdx.y * 64;
    __shared__ float As[32][64];
    __shared__ float Bs[32][64];
    const float* A = g_C1 + (size_t)b * NP;
    int tid = threadIdx.x;
    int ti = tid >> 4, tj = tid & 15;
    float acc[4][4];
    #pragma unroll
    for (int r = 0; r < 4; r++)
        #pragma unroll
        for (int c = 0; c < 4; c++) acc[r][c] = 0.f;

    for (int k0 = 0; k0 < HW; k0 += 32) {
        if (mat == 0) {
            int i = tid >> 2;
            int kq = (tid & 3) * 8;
            float4 va0 = *(const float4*)&A[(i0+i)*HW + k0 + kq];
            float4 va1 = *(const float4*)&A[(i0+i)*HW + k0 + kq + 4];
            As[kq+0][i]=va0.x; As[kq+1][i]=va0.y; As[kq+2][i]=va0.z; As[kq+3][i]=va0.w;
            As[kq+4][i]=va1.x; As[kq+5][i]=va1.y; As[kq+6][i]=va1.z; As[kq+7][i]=va1.w;
            float4 vb0 = *(const float4*)&A[(j0+i)*HW + k0 + kq];
            float4 vb1 = *(const float4*)&A[(j0+i)*HW + k0 + kq + 4];
            Bs[kq+0][i]=vb0.x; Bs[kq+1][i]=vb0.y; Bs[kq+2][i]=vb0.z; Bs[kq+3][i]=vb0.w;
            Bs[kq+4][i]=vb1.x; Bs[kq+5][i]=vb1.y; Bs[kq+6][i]=vb1.z; Bs[kq+7][i]=vb1.w;
        } else {
            int k = tid >> 3, iq = (tid & 7) * 8;
            *(float4*)&As[k][iq]   = *(const float4*)&A[(k0+k)*HW + i0 + iq];
            *(float4*)&As[k][iq+4] = *(const float4*)&A[(k0+k)*HW + i0 + iq + 4];
            *(float4*)&Bs[k][iq]   = *(const float4*)&A[(k0+k)*HW + j0 + iq];
            *(float4*)&Bs[k][iq+4] = *(const float4*)&A[(k0+k)*HW + j0 + iq + 4];
        }
        __syncthreads();
        #pragma unroll
        for (int kk = 0; kk < 32; kk++) {
            float4 a4 = *(float4*)&As[kk][ti*4];
            float4 b4 = *(float4*)&Bs[kk][tj*4];
            float av[4] = {a4.x,a4.y,a4.z,a4.w};
            float bv[4] = {b4.x,b4.y,b4.z,b4.w};
            #pragma unroll
            for (int r = 0; r < 4; r++)
                #pragma unroll
                for (int c = 0; c < 4; c++) acc[r][c] = fmaf(av[r], bv[c], acc[r][c]);
        }
        __syncthreads();
    }
    float* G = g_G + ((size_t)(mat*NB + b)) * HW * HW;
    #pragma unroll
    for (int r = 0; r < 4; r++) {
        float4 v; v.x=acc[r][0]; v.y=acc[r][1]; v.z=acc[r][2]; v.w=acc[r][3];
        *(float4*)&G[(i0 + ti*4 + r)*HW + j0 + tj*4] = v;
    }
}

// ---------------- K2b: row softmax -> S1,S2 (outputs), S12 (tf32-rounded) -----
__global__ __launch_bounds__(256) void k2b_softmax(float* __restrict__ S1o,
                                                   float* __restrict__ S2o) {
    int i = blockIdx.x, b = blockIdx.y, tid = threadIdx.x;
    __shared__ float red[8];
    __shared__ float bc;
    float rr[2];
    #pragma unroll
    for (int mat = 0; mat < 2; mat++) {
        float v = g_G[(((size_t)(mat*NB + b))*HW + i)*HW + tid];
        float m = v;
        #pragma unroll
        for (int o = 16; o; o >>= 1) m = fmaxf(m, __shfl_xor_sync(0xffffffffu, m, o));
        if ((tid & 31) == 0) red[tid >> 5] = m;
        __syncthreads();
        if (tid == 0) {
            float t = red[0];
            #pragma unroll
            for (int j = 1; j < 8; j++) t = fmaxf(t, red[j]);
            bc = t;
        }
        __syncthreads();
        float e = expf(v - bc);
        float s = e;
        #pragma unroll
        for (int o = 16; o; o >>= 1) s += __shfl_xor_sync(0xffffffffu, s, o);
        if ((tid & 31) == 0) red[tid >> 5] = s;
        __syncthreads();
        if (tid == 0) {
            float t = 0.f;
            #pragma unroll
            for (int j = 0; j < 8; j++) t += red[j];
            bc = t;
        }
        __syncthreads();
        rr[mat] = e / bc;
        float* dst = mat == 0 ? S1o : S2o;
        dst[((size_t)b*HW + i)*HW + tid] = rr[mat];
        __syncthreads();
    }
    g_S12[((size_t)b*HW + i)*HW + tid] = to_tf32(rr[0] + rr[1]);
}

// ---------------- K3: tensor-core batched GEMM M = S12 @ C2view (tf32 HMMA) ---
// Per batch: A (256x256) @ B (256x16384). Block tile 128x128, BK=32.
// 8 warps in 4(m) x 2(n), warp tile 32x64, mma.m16n8k8.tf32, fp32 accum.
__global__ __launch_bounds__(256, 2) void k3_bgemm_tc() {
    __shared__ float As[128][36];    // stride 36 floats: A-frag loads conflict-free
    __shared__ float Bs[32][136];    // stride 136 floats: B-frag loads conflict-free
    int b = blockIdx.z;
    int m0 = blockIdx.y * 128;
    int n0 = blockIdx.x * 128;
    const float* Ag = g_S12 + (size_t)b * HW * HW;
    const float* Bg = g_C2t + (size_t)b * NC * NP;
    int tid = threadIdx.x;
    int lane = tid & 31;
    int warp = tid >> 5;
    int wm = warp >> 1;          // 0..3 -> m offset wm*32
    int wn = warp & 1;           // 0..1 -> n offset wn*64
    int g = lane >> 2, tig = lane & 3;

    float acc[2][8][4];
    #pragma unroll
    for (int mf = 0; mf < 2; mf++)
        #pragma unroll
        for (int nf = 0; nf < 8; nf++)
            #pragma unroll
            for (int r = 0; r < 4; r++) acc[mf][nf][r] = 0.f;

    for (int k0 = 0; k0 < HW; k0 += 32) {
        // load A tile 128x32 floats = 1024 float4 (4 per thread)
        #pragma unroll
        for (int t = 0; t < 4; t++) {
            int idx = tid + t*256;
            int row = idx >> 3, q = idx & 7;
            *(float4*)&As[row][q*4] = *(const float4*)&Ag[(size_t)(m0+row)*HW + k0 + q*4];
        }
        // load B tile 32x128 floats = 1024 float4 (4 per thread)
        #pragma unroll
        for (int t = 0; t < 4; t++) {
            int idx = tid + t*256;
            int row = idx >> 5, q = idx & 31;
            *(float4*)&Bs[row][q*4] = *(const float4*)&Bg[(size_t)(k0+row)*CW + n0 + q*4];
        }
        __syncthreads();

        #pragma unroll
        for (int kk = 0; kk < 32; kk += 8) {
            uint32_t a[2][4];
            #pragma unroll
            for (int mf = 0; mf < 2; mf++) {
                int r = wm*32 + mf*16 + g;
                a[mf][0] = __float_as_uint(As[r][kk + tig]);
                a[mf][1] = __float_as_uint(As[r+8][kk + tig]);
                a[mf][2] = __float_as_uint(As[r][kk + tig + 4]);
                a[mf][3] = __float_as_uint(As[r+8][kk + tig + 4]);
            }
            #pragma unroll
            for (int nf = 0; nf < 8; nf++) {
                int c = wn*64 + nf*8 + g;
                uint32_t b0 = __float_as_uint(Bs[kk + tig][c]);
                uint32_t b1 = __float_as_uint(Bs[kk + tig + 4][c]);
                #pragma unroll
                for (int mf = 0; mf < 2; mf++) {
                    asm volatile(
                        "mma.sync.aligned.m16n8k8.row.col.f32.tf32.tf32.f32 "
                        "{%0,%1,%2,%3}, {%4,%5,%6,%7}, {%8,%9}, {%0,%1,%2,%3};"
                        : "+f"(acc[mf][nf][0]), "+f"(acc[mf][nf][1]),
                          "+f"(acc[mf][nf][2]), "+f"(acc[mf][nf][3])
                        : "r"(a[mf][0]), "r"(a[mf][1]), "r"(a[mf][2]), "r"(a[mf][3]),
                          "r"(b0), "r"(b1));
                }
            }
        }
        __syncthreads();
    }

    float* Mp = g_M + (size_t)b * NC * NP;
    #pragma unroll
    for (int mf = 0; mf < 2; mf++) {
        #pragma unroll
        for (int nf = 0; nf < 8; nf++) {
            int row0 = m0 + wm*32 + mf*16 + g;
            int col  = n0 + wn*64 + nf*8 + tig*2;
            float2 v0; v0.x = acc[mf][nf][0]; v0.y = acc[mf][nf][1];
            float2 v1; v1.x = acc[mf][nf][2]; v1.y = acc[mf][nf][3];
            *(float2*)&Mp[(size_t)row0*CW + col] = v0;
            *(float2*)&Mp[(size_t)(row0+8)*CW + col] = v1;
        }
    }
}

// ---------------- K4: C3 = lrelu(fold(M . wO)); out = C2 + C3 ------------------
__global__ __launch_bounds__(256) void k4_out(float* __restrict__ out) {
    __shared__ float wT[NC*NC];
    __shared__ float xs[NC*128];
    int b = blockIdx.y;
    int p0 = blockIdx.x * 128;
    int tid = threadIdx.x;

    for (int i = tid; i < NC*NC; i += 256) wT[i] = g_wOfT[i];

    const float* mb = g_M + (size_t)b * NC * NP;
    float4* xs4 = (float4*)xs;
    for (int i = tid; i < NC*32; i += 256) {
        int c = i >> 5, pq = i & 31;
        xs4[i] = ((const float4*)(mb + (size_t)c*NP + p0))[pq];
    }
    __syncthreads();

    int og = tid >> 4, pg = tid & 15;
    float acc[4][8];
    #pragma unroll
    for (int r = 0; r < 4; r++)
        #pragma unroll
        for (int p = 0; p < 8; p++) acc[r][p] = 0.f;

    #pragma unroll 8
    for (int k = 0; k < NC; k++) {
        float4 a = *(float4*)&wT[k*NC + og*4];
        float4 b0 = *(float4*)&xs[k*128 + pg*8];
        float4 b1v = *(float4*)&xs[k*128 + pg*8 + 4];
        float av[4] = {a.x, a.y, a.z, a.w};
        float bv[8] = {b0.x, b0.y, b0.z, b0.w, b1v.x, b1v.y, b1v.z, b1v.w};
        #pragma unroll
        for (int r = 0; r < 4; r++)
            #pragma unroll
            for (int p = 0; p < 8; p++) acc[r][p] = fmaf(av[r], bv[p], acc[r][p]);
    }

    #pragma unroll
    for (int r = 0; r < 4; r++) {
        int o = og*4 + r;
        float bo = g_bOf[o];
        const float* c2p = &g_C2[(size_t)b*NC*NP + (size_t)o*NP + p0 + pg*8];
        float4 c20 = *(const float4*)c2p;
        float4 c21 = *(const float4*)(c2p + 4);
        float4 y0, y1;
        y0.x = c20.x + lrelu(acc[r][0]+bo); y0.y = c20.y + lrelu(acc[r][1]+bo);
        y0.z = c20.z + lrelu(acc[r][2]+bo); y0.w = c20.w + lrelu(acc[r][3]+bo);
        y1.x = c21.x + lrelu(acc[r][4]+bo); y1.y = c21.y + lrelu(acc[r][5]+bo);
        y1.z = c21.z + lrelu(acc[r][6]+bo); y1.w = c21.w + lrelu(acc[r][7]+bo);
        float* dst = &out[(size_t)b*NC*NP + (size_t)o*NP + p0 + pg*8];
        *(float4*)dst = y0;
        *(float4*)(dst+4) = y1;
    }
}

// ---------------- launch --------------------------------------------------------
extern "C" void kernel_launch(void* const* d_in, const int* in_sizes, int n_in,
                              void* d_out, int out_size) {
    const float* x   = (const float*)d_in[0];
    const float* w1  = (const float*)d_in[1];
    const float* b1  = (const float*)d_in[2];
    const float* g1  = (const float*)d_in[3];
    const float* be1 = (const float*)d_in[4];
    const float* m1  = (const float*)d_in[5];
    const float* v1  = (const float*)d_in[6];
    const float* wA  = (const float*)d_in[7];
    const float* bA  = (const float*)d_in[8];
    const float* gA  = (const float*)d_in[9];
    const float* beA = (const float*)d_in[10];
    const float* mA  = (const float*)d_in[11];
    const float* vA  = (const float*)d_in[12];
    const float* wO  = (const float*)d_in[13];
    const float* bO  = (const float*)d_in[14];
    const float* gO  = (const float*)d_in[15];
    const float* beO = (const float*)d_in[16];
    const float* mO  = (const float*)d_in[17];
    const float* vO  = (const float*)d_in[18];

    float* out = (float*)d_out;
    float* S1o = out + (size_t)C2ELEMS;
    float* S2o = S1o + (size_t)SELEMS;

    k0_fold<<<1, 64>>>(w1,b1,g1,be1,m1,v1, wA,bA,gA,beA,mA,vA, wO,bO,gO,beO,mO,vO);
    k1_c1c2<<<dim3(NP/128, NB), 256>>>(x);
    k2a_gram<<<dim3(4, 4, 2*NB), 256>>>();
    k2b_softmax<<<dim3(HW, NB), 256>>>(S1o, S2o);
    k3_bgemm_tc<<<dim3(CW/128, HW/128, NB), 256>>>();
    k4_out<<<dim3(NP/128, NB), 256>>>(out);
}

// round 6
// speedup vs baseline: 2.0206x; 1.3603x over previous
#include <cuda_runtime.h>
#include <cuda_bf16.h>
#include <cstdint>

// Problem constants: B=8, C=64, H=W=256
#define NB 8
#define NC 64
#define NP 65536              // H*W
#define HW 256                // H (== W)
#define CW 16384              // C*W
#define C2ELEMS (NB*NC*NP)    // 33554432
#define SELEMS  (NB*HW*HW)    // 524288
#define EPSBN 1e-5f
#define SLOPE 0.2f

// ---------------- scratch (device globals; no allocation allowed) -------------
__device__ float g_w1f[NC];
__device__ float g_b1f;
__device__ float g_wAhi[NC*NC];   // [o][c] row-major, tf32 hi part (BN-folded)
__device__ float g_wAlo[NC*NC];   // lo part
__device__ float g_bAf[NC];
__device__ float g_wOhi[NC*NC];
__device__ float g_wOlo[NC*NC];
__device__ float g_bOf[NC];
__device__ float g_C1[NB*NP];                 // (B,H,W)  2MB
__device__ float g_C2[C2ELEMS];               // (B,C,H,W) fp32 (residual + GEMM src)
__device__ float g_G[2*NB*HW*HW];             // gram matrices, 4MB
__device__ float g_S12[SELEMS];               // S1+S2, tf32-rounded, 2MB
__device__ float g_M[C2ELEMS];                // (S1+S2)@C2view, 134MB

__device__ __forceinline__ float lrelu(float y) { return y >= 0.f ? y : SLOPE * y; }

__device__ __forceinline__ float to_tf32(float x) {
    uint32_t r;
    asm("cvt.rna.tf32.f32 %0, %1;" : "=r"(r) : "f"(x));
    return __uint_as_float(r);
}

__device__ __forceinline__ void mma_tf32(float acc[4],
                                         uint32_t a0, uint32_t a1, uint32_t a2, uint32_t a3,
                                         uint32_t b0, uint32_t b1) {
    asm volatile(
        "mma.sync.aligned.m16n8k8.row.col.f32.tf32.tf32.f32 "
        "{%0,%1,%2,%3}, {%4,%5,%6,%7}, {%8,%9}, {%0,%1,%2,%3};"
        : "+f"(acc[0]), "+f"(acc[1]), "+f"(acc[2]), "+f"(acc[3])
        : "r"(a0), "r"(a1), "r"(a2), "r"(a3), "r"(b0), "r"(b1));
}

// ---------------- K0: fold BN into conv weights; split into tf32 hi/lo --------
__global__ void k0_fold(const float* __restrict__ w1, const float* __restrict__ b1,
                        const float* __restrict__ g1, const float* __restrict__ be1,
                        const float* __restrict__ m1, const float* __restrict__ v1,
                        const float* __restrict__ wA, const float* __restrict__ bA,
                        const float* __restrict__ gA, const float* __restrict__ beA,
                        const float* __restrict__ mA, const float* __restrict__ vA,
                        const float* __restrict__ wO, const float* __restrict__ bO,
                        const float* __restrict__ gO, const float* __restrict__ beO,
                        const float* __restrict__ mO, const float* __restrict__ vO) {
    int o = threadIdx.x;  // 0..63
    float aA = gA[o] * rsqrtf(vA[o] + EPSBN);
    float aO = gO[o] * rsqrtf(vO[o] + EPSBN);
    for (int c = 0; c < NC; c++) {
        float wa = aA * wA[o*NC + c];
        float hA = to_tf32(wa);
        g_wAhi[o*NC + c] = hA;
        g_wAlo[o*NC + c] = to_tf32(wa - hA);
        float wo = aO * wO[o*NC + c];
        float hO = to_tf32(wo);
        g_wOhi[o*NC + c] = hO;
        g_wOlo[o*NC + c] = to_tf32(wo - hO);
    }
    g_bAf[o] = aA * (bA[o] - mA[o]) + beA[o];
    g_bOf[o] = aO * (bO[o] - mO[o]) + beO[o];
    float a1 = g1[0] * rsqrtf(v1[0] + EPSBN);
    g_w1f[o] = a1 * w1[o];
    if (o == 0) g_b1f = a1 * (b1[0] - m1[0]) + be1[0];
}

// ---------------- K1: fused C1 (fp32) + C2 conv via 3xTF32 MMA ----------------
// grid (NP/128, NB), 256 threads (8 warps: 4m x 2n, warp tile 16(o) x 64(p)).
__global__ __launch_bounds__(256) void k1_c1c2(const float* __restrict__ x) {
    __shared__ float xs[NC][136];   // [c][p], stride 136 -> conflict-free frags
    int b = blockIdx.y;
    int p0 = blockIdx.x * 128;
    int tid = threadIdx.x;

    const float* xb = x + (size_t)b * NC * NP;
    // load 64x128 fp32 tile = 2048 float4, 8 per thread
    #pragma unroll
    for (int t = 0; t < 8; t++) {
        int i = tid + t*256;            // 0..2047
        int c = i >> 5, pq = i & 31;    // c 0..63, pq 0..31
        *(float4*)&xs[c][pq*4] = *(const float4*)(xb + (size_t)c*NP + p0 + pq*4);
    }
    __syncthreads();

    // C1 for these 128 pixels (exact fp32 — feeds softmax outputs)
    if (tid < 128) {
        float s = 0.f;
        #pragma unroll
        for (int c = 0; c < NC; c++) s += g_w1f[c] * xs[c][tid];
        s += g_b1f;
        g_C1[(size_t)b*NP + p0 + tid] = lrelu(s);
    }

    int lane = tid & 31, warp = tid >> 5;
    int wm = warp >> 1;           // 0..3 -> o base wm*16
    int wn = warp & 1;            // 0..1 -> p base wn*64
    int g = lane >> 2, tig = lane & 3;
    int r0 = wm*16 + g;

    float acc[8][4];
    #pragma unroll
    for (int nf = 0; nf < 8; nf++)
        #pragma unroll
        for (int r = 0; r < 4; r++) acc[nf][r] = 0.f;

    #pragma unroll
    for (int kk = 0; kk < NC; kk += 8) {
        uint32_t ah0 = __float_as_uint(g_wAhi[r0*NC + kk + tig]);
        uint32_t ah1 = __float_as_uint(g_wAhi[(r0+8)*NC + kk + tig]);
        uint32_t ah2 = __float_as_uint(g_wAhi[r0*NC + kk + tig + 4]);
        uint32_t ah3 = __float_as_uint(g_wAhi[(r0+8)*NC + kk + tig + 4]);
        uint32_t al0 = __float_as_uint(g_wAlo[r0*NC + kk + tig]);
        uint32_t al1 = __float_as_uint(g_wAlo[(r0+8)*NC + kk + tig]);
        uint32_t al2 = __float_as_uint(g_wAlo[r0*NC + kk + tig + 4]);
        uint32_t al3 = __float_as_uint(g_wAlo[(r0+8)*NC + kk + tig + 4]);
        #pragma unroll
        for (int nf = 0; nf < 8; nf++) {
            int c0 = wn*64 + nf*8 + g;
            float x0 = xs[kk + tig][c0];
            float x1 = xs[kk + tig + 4][c0];
            float h0 = to_tf32(x0), h1 = to_tf32(x1);
            float l0 = to_tf32(x0 - h0), l1 = to_tf32(x1 - h1);
            uint32_t bh0 = __float_as_uint(h0), bh1 = __float_as_uint(h1);
            uint32_t bl0 = __float_as_uint(l0), bl1 = __float_as_uint(l1);
            mma_tf32(acc[nf], ah0, ah1, ah2, ah3, bh0, bh1);
            mma_tf32(acc[nf], ah0, ah1, ah2, ah3, bl0, bl1);
            mma_tf32(acc[nf], al0, al1, al2, al3, bh0, bh1);
        }
    }

    int o0 = wm*16 + g, o1 = o0 + 8;
    float bo0 = g_bAf[o0], bo1 = g_bAf[o1];
    #pragma unroll
    for (int nf = 0; nf < 8; nf++) {
        int col = p0 + wn*64 + nf*8 + tig*2;
        float2 v0, v1;
        v0.x = lrelu(acc[nf][0] + bo0); v0.y = lrelu(acc[nf][1] + bo0);
        v1.x = lrelu(acc[nf][2] + bo1); v1.y = lrelu(acc[nf][3] + bo1);
        *(float2*)&g_C2[(size_t)b*NC*NP + (size_t)o0*NP + col] = v0;
        *(float2*)&g_C2[(size_t)b*NC*NP + (size_t)o1*NP + col] = v1;
    }
}

// ---------------- K2a: Gram matrices G1 = C1 C1^T, G2 = C1^T C1 ---------------
__global__ __launch_bounds__(256) void k2a_gram() {
    int mat = blockIdx.z & 1;
    int b = blockIdx.z >> 1;
    int j0 = blockIdx.x * 64;
    int i0 = blockIdx.y * 64;
    __shared__ float As[32][64];
    __shared__ float Bs[32][64];
    const float* A = g_C1 + (size_t)b * NP;
    int tid = threadIdx.x;
    int ti = tid >> 4, tj = tid & 15;
    float acc[4][4];
    #pragma unroll
    for (int r = 0; r < 4; r++)
        #pragma unroll
        for (int c = 0; c < 4; c++) acc[r][c] = 0.f;

    for (int k0 = 0; k0 < HW; k0 += 32) {
        if (mat == 0) {
            int i = tid >> 2;
            int kq = (tid & 3) * 8;
            float4 va0 = *(const float4*)&A[(i0+i)*HW + k0 + kq];
            float4 va1 = *(const float4*)&A[(i0+i)*HW + k0 + kq + 4];
            As[kq+0][i]=va0.x; As[kq+1][i]=va0.y; As[kq+2][i]=va0.z; As[kq+3][i]=va0.w;
            As[kq+4][i]=va1.x; As[kq+5][i]=va1.y; As[kq+6][i]=va1.z; As[kq+7][i]=va1.w;
            float4 vb0 = *(const float4*)&A[(j0+i)*HW + k0 + kq];
            float4 vb1 = *(const float4*)&A[(j0+i)*HW + k0 + kq + 4];
            Bs[kq+0][i]=vb0.x; Bs[kq+1][i]=vb0.y; Bs[kq+2][i]=vb0.z; Bs[kq+3][i]=vb0.w;
            Bs[kq+4][i]=vb1.x; Bs[kq+5][i]=vb1.y; Bs[kq+6][i]=vb1.z; Bs[kq+7][i]=vb1.w;
        } else {
            int k = tid >> 3, iq = (tid & 7) * 8;
            *(float4*)&As[k][iq]   = *(const float4*)&A[(k0+k)*HW + i0 + iq];
            *(float4*)&As[k][iq+4] = *(const float4*)&A[(k0+k)*HW + i0 + iq + 4];
            *(float4*)&Bs[k][iq]   = *(const float4*)&A[(k0+k)*HW + j0 + iq];
            *(float4*)&Bs[k][iq+4] = *(const float4*)&A[(k0+k)*HW + j0 + iq + 4];
        }
        __syncthreads();
        #pragma unroll
        for (int kk = 0; kk < 32; kk++) {
            float4 a4 = *(float4*)&As[kk][ti*4];
            float4 b4 = *(float4*)&Bs[kk][tj*4];
            float av[4] = {a4.x,a4.y,a4.z,a4.w};
            float bv[4] = {b4.x,b4.y,b4.z,b4.w};
            #pragma unroll
            for (int r = 0; r < 4; r++)
                #pragma unroll
                for (int c = 0; c < 4; c++) acc[r][c] = fmaf(av[r], bv[c], acc[r][c]);
        }
        __syncthreads();
    }
    float* G = g_G + ((size_t)(mat*NB + b)) * HW * HW;
    #pragma unroll
    for (int r = 0; r < 4; r++) {
        float4 v; v.x=acc[r][0]; v.y=acc[r][1]; v.z=acc[r][2]; v.w=acc[r][3];
        *(float4*)&G[(i0 + ti*4 + r)*HW + j0 + tj*4] = v;
    }
}

// ---------------- K2b: row softmax -> S1,S2 (outputs), S12 (tf32-rounded) -----
__global__ __launch_bounds__(256) void k2b_softmax(float* __restrict__ S1o,
                                                   float* __restrict__ S2o) {
    int i = blockIdx.x, b = blockIdx.y, tid = threadIdx.x;
    __shared__ float red[8];
    __shared__ float bc;
    float rr[2];
    #pragma unroll
    for (int mat = 0; mat < 2; mat++) {
        float v = g_G[(((size_t)(mat*NB + b))*HW + i)*HW + tid];
        float m = v;
        #pragma unroll
        for (int o = 16; o; o >>= 1) m = fmaxf(m, __shfl_xor_sync(0xffffffffu, m, o));
        if ((tid & 31) == 0) red[tid >> 5] = m;
        __syncthreads();
        if (tid == 0) {
            float t = red[0];
            #pragma unroll
            for (int j = 1; j < 8; j++) t = fmaxf(t, red[j]);
            bc = t;
        }
        __syncthreads();
        float e = expf(v - bc);
        float s = e;
        #pragma unroll
        for (int o = 16; o; o >>= 1) s += __shfl_xor_sync(0xffffffffu, s, o);
        if ((tid & 31) == 0) red[tid >> 5] = s;
        __syncthreads();
        if (tid == 0) {
            float t = 0.f;
            #pragma unroll
            for (int j = 0; j < 8; j++) t += red[j];
            bc = t;
        }
        __syncthreads();
        rr[mat] = e / bc;
        float* dst = mat == 0 ? S1o : S2o;
        dst[((size_t)b*HW + i)*HW + tid] = rr[mat];
        __syncthreads();
    }
    g_S12[((size_t)b*HW + i)*HW + tid] = to_tf32(rr[0] + rr[1]);
}

// ---------------- K3: tensor-core batched GEMM M = S12 @ C2view (tf32 HMMA) ---
// Per batch: A (256x256) @ B (256x16384). Block tile 128x128, BK=32.
// B read from fp32 C2, tf32-rounded once during smem fill.
__global__ __launch_bounds__(256, 2) void k3_bgemm_tc() {
    __shared__ float As[128][36];
    __shared__ float Bs[32][136];
    int b = blockIdx.z;
    int m0 = blockIdx.y * 128;
    int n0 = blockIdx.x * 128;
    const float* Ag = g_S12 + (size_t)b * HW * HW;
    const float* Bg = g_C2 + (size_t)b * NC * NP;
    int tid = threadIdx.x;
    int lane = tid & 31;
    int warp = tid >> 5;
    int wm = warp >> 1;
    int wn = warp & 1;
    int g = lane >> 2, tig = lane & 3;

    float acc[2][8][4];
    #pragma unroll
    for (int mf = 0; mf < 2; mf++)
        #pragma unroll
        for (int nf = 0; nf < 8; nf++)
            #pragma unroll
            for (int r = 0; r < 4; r++) acc[mf][nf][r] = 0.f;

    for (int k0 = 0; k0 < HW; k0 += 32) {
        // A tile 128x32 = 1024 float4 (4/thread), already tf32-rounded in k2b
        #pragma unroll
        for (int t = 0; t < 4; t++) {
            int idx = tid + t*256;
            int row = idx >> 3, q = idx & 7;
            *(float4*)&As[row][q*4] = *(const float4*)&Ag[(size_t)(m0+row)*HW + k0 + q*4];
        }
        // B tile 32x128 = 1024 float4 (4/thread), round to tf32 here
        #pragma unroll
        for (int t = 0; t < 4; t++) {
            int idx = tid + t*256;
            int row = idx >> 5, q = idx & 31;
            float4 v = *(const float4*)&Bg[(size_t)(k0+row)*CW + n0 + q*4];
            v.x = to_tf32(v.x); v.y = to_tf32(v.y);
            v.z = to_tf32(v.z); v.w = to_tf32(v.w);
            *(float4*)&Bs[row][q*4] = v;
        }
        __syncthreads();

        #pragma unroll
        for (int kk = 0; kk < 32; kk += 8) {
            uint32_t a[2][4];
            #pragma unroll
            for (int mf = 0; mf < 2; mf++) {
                int r = wm*32 + mf*16 + g;
                a[mf][0] = __float_as_uint(As[r][kk + tig]);
                a[mf][1] = __float_as_uint(As[r+8][kk + tig]);
                a[mf][2] = __float_as_uint(As[r][kk + tig + 4]);
                a[mf][3] = __float_as_uint(As[r+8][kk + tig + 4]);
            }
            #pragma unroll
            for (int nf = 0; nf < 8; nf++) {
                int c = wn*64 + nf*8 + g;
                uint32_t b0 = __float_as_uint(Bs[kk + tig][c]);
                uint32_t b1 = __float_as_uint(Bs[kk + tig + 4][c]);
                #pragma unroll
                for (int mf = 0; mf < 2; mf++)
                    mma_tf32(acc[mf][nf], a[mf][0], a[mf][1], a[mf][2], a[mf][3], b0, b1);
            }
        }
        __syncthreads();
    }

    float* Mp = g_M + (size_t)b * NC * NP;
    #pragma unroll
    for (int mf = 0; mf < 2; mf++) {
        #pragma unroll
        for (int nf = 0; nf < 8; nf++) {
            int row0 = m0 + wm*32 + mf*16 + g;
            int col  = n0 + wn*64 + nf*8 + tig*2;
            float2 v0; v0.x = acc[mf][nf][0]; v0.y = acc[mf][nf][1];
            float2 v1; v1.x = acc[mf][nf][2]; v1.y = acc[mf][nf][3];
            *(float2*)&Mp[(size_t)row0*CW + col] = v0;
            *(float2*)&Mp[(size_t)(row0+8)*CW + col] = v1;
        }
    }
}

// ---------------- K4: C3 = lrelu(Wo.M + b); out = C2 + C3 via 3xTF32 MMA ------
// grid (NP/128, NB), 256 threads; same structure as K1.
__global__ __launch_bounds__(256) void k4_out(float* __restrict__ out) {
    __shared__ float ms[NC][136];
    int b = blockIdx.y;
    int p0 = blockIdx.x * 128;
    int tid = threadIdx.x;

    const float* mb = g_M + (size_t)b * NC * NP;
    #pragma unroll
    for (int t = 0; t < 8; t++) {
        int i = tid + t*256;
        int c = i >> 5, pq = i & 31;
        *(float4*)&ms[c][pq*4] = *(const float4*)(mb + (size_t)c*NP + p0 + pq*4);
    }
    __syncthreads();

    int lane = tid & 31, warp = tid >> 5;
    int wm = warp >> 1;
    int wn = warp & 1;
    int g = lane >> 2, tig = lane & 3;
    int r0 = wm*16 + g;

    float acc[8][4];
    #pragma unroll
    for (int nf = 0; nf < 8; nf++)
        #pragma unroll
        for (int r = 0; r < 4; r++) acc[nf][r] = 0.f;

    #pragma unroll
    for (int kk = 0; kk < NC; kk += 8) {
        uint32_t ah0 = __float_as_uint(g_wOhi[r0*NC + kk + tig]);
        uint32_t ah1 = __float_as_uint(g_wOhi[(r0+8)*NC + kk + tig]);
        uint32_t ah2 = __float_as_uint(g_wOhi[r0*NC + kk + tig + 4]);
        uint32_t ah3 = __float_as_uint(g_wOhi[(r0+8)*NC + kk + tig + 4]);
        uint32_t al0 = __float_as_uint(g_wOlo[r0*NC + kk + tig]);
        uint32_t al1 = __float_as_uint(g_wOlo[(r0+8)*NC + kk + tig]);
        uint32_t al2 = __float_as_uint(g_wOlo[r0*NC + kk + tig + 4]);
        uint32_t al3 = __float_as_uint(g_wOlo[(r0+8)*NC + kk + tig + 4]);
        #pragma unroll
        for (int nf = 0; nf < 8; nf++) {
            int c0 = wn*64 + nf*8 + g;
            float x0 = ms[kk + tig][c0];
            float x1 = ms[kk + tig + 4][c0];
            float h0 = to_tf32(x0), h1 = to_tf32(x1);
            float l0 = to_tf32(x0 - h0), l1 = to_tf32(x1 - h1);
            uint32_t bh0 = __float_as_uint(h0), bh1 = __float_as_uint(h1);
            uint32_t bl0 = __float_as_uint(l0), bl1 = __float_as_uint(l1);
            mma_tf32(acc[nf], ah0, ah1, ah2, ah3, bh0, bh1);
            mma_tf32(acc[nf], ah0, ah1, ah2, ah3, bl0, bl1);
            mma_tf32(acc[nf], al0, al1, al2, al3, bh0, bh1);
        }
    }

    int o0 = wm*16 + g, o1 = o0 + 8;
    float bo0 = g_bOf[o0], bo1 = g_bOf[o1];
    #pragma unroll
    for (int nf = 0; nf < 8; nf++) {
        int col = p0 + wn*64 + nf*8 + tig*2;
        size_t off0 = (size_t)b*NC*NP + (size_t)o0*NP + col;
        size_t off1 = (size_t)b*NC*NP + (size_t)o1*NP + col;
        float2 c20 = *(const float2*)&g_C2[off0];
        float2 c21 = *(const float2*)&g_C2[off1];
        float2 v0, v1;
        v0.x = c20.x + lrelu(acc[nf][0] + bo0);
        v0.y = c20.y + lrelu(acc[nf][1] + bo0);
        v1.x = c21.x + lrelu(acc[nf][2] + bo1);
        v1.y = c21.y + lrelu(acc[nf][3] + bo1);
        *(float2*)&out[off0] = v0;
        *(float2*)&out[off1] = v1;
    }
}

// ---------------- launch --------------------------------------------------------
extern "C" void kernel_launch(void* const* d_in, const int* in_sizes, int n_in,
                              void* d_out, int out_size) {
    const float* x   = (const float*)d_in[0];
    const float* w1  = (const float*)d_in[1];
    const float* b1  = (const float*)d_in[2];
    const float* g1  = (const float*)d_in[3];
    const float* be1 = (const float*)d_in[4];
    const float* m1  = (const float*)d_in[5];
    const float* v1  = (const float*)d_in[6];
    const float* wA  = (const float*)d_in[7];
    const float* bA  = (const float*)d_in[8];
    const float* gA  = (const float*)d_in[9];
    const float* beA = (const float*)d_in[10];
    const float* mA  = (const float*)d_in[11];
    const float* vA  = (const float*)d_in[12];
    const float* wO  = (const float*)d_in[13];
    const float* bO  = (const float*)d_in[14];
    const float* gO  = (const float*)d_in[15];
    const float* beO = (const float*)d_in[16];
    const float* mO  = (const float*)d_in[17];
    const float* vO  = (const float*)d_in[18];

    float* out = (float*)d_out;
    float* S1o = out + (size_t)C2ELEMS;
    float* S2o = S1o + (size_t)SELEMS;

    k0_fold<<<1, 64>>>(w1,b1,g1,be1,m1,v1, wA,bA,gA,beA,mA,vA, wO,bO,gO,beO,mO,vO);
    k1_c1c2<<<dim3(NP/128, NB), 256>>>(x);
    k2a_gram<<<dim3(4, 4, 2*NB), 256>>>();
    k2b_softmax<<<dim3(HW, NB), 256>>>(S1o, S2o);
    k3_bgemm_tc<<<dim3(CW/128, HW/128, NB), 256>>>();
    k4_out<<<dim3(NP/128, NB), 256>>>(out);
}

// round 7
// speedup vs baseline: 2.3751x; 1.1754x over previous
#include <cuda_runtime.h>
#include <cuda_bf16.h>
#include <cstdint>

// Problem constants: B=8, C=64, H=W=256
#define NB 8
#define NC 64
#define NP 65536              // H*W
#define HW 256                // H (== W)
#define CW 16384              // C*W
#define C2ELEMS (NB*NC*NP)    // 33554432
#define SELEMS  (NB*HW*HW)    // 524288
#define EPSBN 1e-5f
#define SLOPE 0.2f

// ---------------- scratch (device globals; no allocation allowed) -------------
__device__ float g_w1f[NC];
__device__ float g_b1f;
__device__ float g_wAt[NC*NC];    // [o][c], tf32-rounded, BN-folded
__device__ float g_bAf[NC];
__device__ float g_wOt[NC*NC];    // [o][c], tf32-rounded, BN-folded
__device__ float g_bOf[NC];
__device__ float g_C1[NB*NP];                 // (B,H,W)  2MB
__device__ float g_C2[C2ELEMS];               // (B,C,H,W) fp32 (GEMM src + residual)
__device__ float g_G[2*NB*HW*HW];             // gram matrices, 4MB
__device__ float g_S12[SELEMS];               // S1+S2, tf32-rounded, 2MB

__device__ __forceinline__ float lrelu(float y) { return y >= 0.f ? y : SLOPE * y; }

__device__ __forceinline__ float to_tf32(float x) {
    uint32_t r;
    asm("cvt.rna.tf32.f32 %0, %1;" : "=r"(r) : "f"(x));
    return __uint_as_float(r);
}

__device__ __forceinline__ void mma_tf32(float acc[4],
                                         uint32_t a0, uint32_t a1, uint32_t a2, uint32_t a3,
                                         uint32_t b0, uint32_t b1) {
    asm volatile(
        "mma.sync.aligned.m16n8k8.row.col.f32.tf32.tf32.f32 "
        "{%0,%1,%2,%3}, {%4,%5,%6,%7}, {%8,%9}, {%0,%1,%2,%3};"
        : "+f"(acc[0]), "+f"(acc[1]), "+f"(acc[2]), "+f"(acc[3])
        : "r"(a0), "r"(a1), "r"(a2), "r"(a3), "r"(b0), "r"(b1));
}

// ---------------- K0: fold BN into conv weights; tf32-round -------------------
__global__ void k0_fold(const float* __restrict__ w1, const float* __restrict__ b1,
                        const float* __restrict__ g1, const float* __restrict__ be1,
                        const float* __restrict__ m1, const float* __restrict__ v1,
                        const float* __restrict__ wA, const float* __restrict__ bA,
                        const float* __restrict__ gA, const float* __restrict__ beA,
                        const float* __restrict__ mA, const float* __restrict__ vA,
                        const float* __restrict__ wO, const float* __restrict__ bO,
                        const float* __restrict__ gO, const float* __restrict__ beO,
                        const float* __restrict__ mO, const float* __restrict__ vO) {
    int o = threadIdx.x;  // 0..63
    float aA = gA[o] * rsqrtf(vA[o] + EPSBN);
    float aO = gO[o] * rsqrtf(vO[o] + EPSBN);
    for (int c = 0; c < NC; c++) {
        g_wAt[o*NC + c] = to_tf32(aA * wA[o*NC + c]);
        g_wOt[o*NC + c] = to_tf32(aO * wO[o*NC + c]);
    }
    g_bAf[o] = aA * (bA[o] - mA[o]) + beA[o];
    g_bOf[o] = aO * (bO[o] - mO[o]) + beO[o];
    float a1 = g1[0] * rsqrtf(v1[0] + EPSBN);
    g_w1f[o] = a1 * w1[o];
    if (o == 0) g_b1f = a1 * (b1[0] - m1[0]) + be1[0];
}

// ---------------- K1: fused C1 (fp32) + C2 conv via 1-pass TF32 MMA -----------
// grid (NP/128, NB), 256 threads (8 warps: 4m x 2n, warp tile 16(o) x 64(p)).
__global__ __launch_bounds__(256) void k1_c1c2(const float* __restrict__ x) {
    __shared__ float xs[NC][136];   // [c][p]
    int b = blockIdx.y;
    int p0 = blockIdx.x * 128;
    int tid = threadIdx.x;

    const float* xb = x + (size_t)b * NC * NP;
    // 64x128 fp32 tile = 2048 float4, 8 per thread
    #pragma unroll
    for (int t = 0; t < 8; t++) {
        int i = tid + t*256;            // 0..2047
        int c = i >> 5, pq = i & 31;
        *(float4*)&xs[c][pq*4] = *(const float4*)(xb + (size_t)c*NP + p0 + pq*4);
    }
    __syncthreads();

    // C1 exact fp32 (feeds softmax outputs)
    if (tid < 128) {
        float s = 0.f;
        #pragma unroll
        for (int c = 0; c < NC; c++) s += g_w1f[c] * xs[c][tid];
        s += g_b1f;
        g_C1[(size_t)b*NP + p0 + tid] = lrelu(s);
    }

    int lane = tid & 31, warp = tid >> 5;
    int wm = warp >> 1;
    int wn = warp & 1;
    int g = lane >> 2, tig = lane & 3;
    int r0 = wm*16 + g;

    float acc[8][4];
    #pragma unroll
    for (int nf = 0; nf < 8; nf++)
        #pragma unroll
        for (int r = 0; r < 4; r++) acc[nf][r] = 0.f;

    #pragma unroll
    for (int kk = 0; kk < NC; kk += 8) {
        uint32_t a0 = __float_as_uint(g_wAt[r0*NC + kk + tig]);
        uint32_t a1 = __float_as_uint(g_wAt[(r0+8)*NC + kk + tig]);
        uint32_t a2 = __float_as_uint(g_wAt[r0*NC + kk + tig + 4]);
        uint32_t a3 = __float_as_uint(g_wAt[(r0+8)*NC + kk + tig + 4]);
        #pragma unroll
        for (int nf = 0; nf < 8; nf++) {
            int c0 = wn*64 + nf*8 + g;
            uint32_t b0 = __float_as_uint(to_tf32(xs[kk + tig][c0]));
            uint32_t b1 = __float_as_uint(to_tf32(xs[kk + tig + 4][c0]));
            mma_tf32(acc[nf], a0, a1, a2, a3, b0, b1);
        }
    }

    int o0 = wm*16 + g, o1 = o0 + 8;
    float bo0 = g_bAf[o0], bo1 = g_bAf[o1];
    #pragma unroll
    for (int nf = 0; nf < 8; nf++) {
        int col = p0 + wn*64 + nf*8 + tig*2;
        float2 v0, v1;
        v0.x = lrelu(acc[nf][0] + bo0); v0.y = lrelu(acc[nf][1] + bo0);
        v1.x = lrelu(acc[nf][2] + bo1); v1.y = lrelu(acc[nf][3] + bo1);
        *(float2*)&g_C2[(size_t)b*NC*NP + (size_t)o0*NP + col] = v0;
        *(float2*)&g_C2[(size_t)b*NC*NP + (size_t)o1*NP + col] = v1;
    }
}

// ---------------- K2a: Gram matrices G1 = C1 C1^T, G2 = C1^T C1 ---------------
__global__ __launch_bounds__(256) void k2a_gram() {
    int mat = blockIdx.z & 1;
    int b = blockIdx.z >> 1;
    int j0 = blockIdx.x * 64;
    int i0 = blockIdx.y * 64;
    __shared__ float As[32][64];
    __shared__ float Bs[32][64];
    const float* A = g_C1 + (size_t)b * NP;
    int tid = threadIdx.x;
    int ti = tid >> 4, tj = tid & 15;
    float acc[4][4];
    #pragma unroll
    for (int r = 0; r < 4; r++)
        #pragma unroll
        for (int c = 0; c < 4; c++) acc[r][c] = 0.f;

    for (int k0 = 0; k0 < HW; k0 += 32) {
        if (mat == 0) {
            int i = tid >> 2;
            int kq = (tid & 3) * 8;
            float4 va0 = *(const float4*)&A[(i0+i)*HW + k0 + kq];
            float4 va1 = *(const float4*)&A[(i0+i)*HW + k0 + kq + 4];
            As[kq+0][i]=va0.x; As[kq+1][i]=va0.y; As[kq+2][i]=va0.z; As[kq+3][i]=va0.w;
            As[kq+4][i]=va1.x; As[kq+5][i]=va1.y; As[kq+6][i]=va1.z; As[kq+7][i]=va1.w;
            float4 vb0 = *(const float4*)&A[(j0+i)*HW + k0 + kq];
            float4 vb1 = *(const float4*)&A[(j0+i)*HW + k0 + kq + 4];
            Bs[kq+0][i]=vb0.x; Bs[kq+1][i]=vb0.y; Bs[kq+2][i]=vb0.z; Bs[kq+3][i]=vb0.w;
            Bs[kq+4][i]=vb1.x; Bs[kq+5][i]=vb1.y; Bs[kq+6][i]=vb1.z; Bs[kq+7][i]=vb1.w;
        } else {
            int k = tid >> 3, iq = (tid & 7) * 8;
            *(float4*)&As[k][iq]   = *(const float4*)&A[(k0+k)*HW + i0 + iq];
            *(float4*)&As[k][iq+4] = *(const float4*)&A[(k0+k)*HW + i0 + iq + 4];
            *(float4*)&Bs[k][iq]   = *(const float4*)&A[(k0+k)*HW + j0 + iq];
            *(float4*)&Bs[k][iq+4] = *(const float4*)&A[(k0+k)*HW + j0 + iq + 4];
        }
        __syncthreads();
        #pragma unroll
        for (int kk = 0; kk < 32; kk++) {
            float4 a4 = *(float4*)&As[kk][ti*4];
            float4 b4 = *(float4*)&Bs[kk][tj*4];
            float av[4] = {a4.x,a4.y,a4.z,a4.w};
            float bv[4] = {b4.x,b4.y,b4.z,b4.w};
            #pragma unroll
            for (int r = 0; r < 4; r++)
                #pragma unroll
                for (int c = 0; c < 4; c++) acc[r][c] = fmaf(av[r], bv[c], acc[r][c]);
        }
        __syncthreads();
    }
    float* G = g_G + ((size_t)(mat*NB + b)) * HW * HW;
    #pragma unroll
    for (int r = 0; r < 4; r++) {
        float4 v; v.x=acc[r][0]; v.y=acc[r][1]; v.z=acc[r][2]; v.w=acc[r][3];
        *(float4*)&G[(i0 + ti*4 + r)*HW + j0 + tj*4] = v;
    }
}

// ---------------- K2b: row softmax -> S1,S2 (outputs), S12 (tf32-rounded) -----
__global__ __launch_bounds__(256) void k2b_softmax(float* __restrict__ S1o,
                                                   float* __restrict__ S2o) {
    int i = blockIdx.x, b = blockIdx.y, tid = threadIdx.x;
    __shared__ float red[8];
    __shared__ float bc;
    float rr[2];
    #pragma unroll
    for (int mat = 0; mat < 2; mat++) {
        float v = g_G[(((size_t)(mat*NB + b))*HW + i)*HW + tid];
        float m = v;
        #pragma unroll
        for (int o = 16; o; o >>= 1) m = fmaxf(m, __shfl_xor_sync(0xffffffffu, m, o));
        if ((tid & 31) == 0) red[tid >> 5] = m;
        __syncthreads();
        if (tid == 0) {
            float t = red[0];
            #pragma unroll
            for (int j = 1; j < 8; j++) t = fmaxf(t, red[j]);
            bc = t;
        }
        __syncthreads();
        float e = expf(v - bc);
        float s = e;
        #pragma unroll
        for (int o = 16; o; o >>= 1) s += __shfl_xor_sync(0xffffffffu, s, o);
        if ((tid & 31) == 0) red[tid >> 5] = s;
        __syncthreads();
        if (tid == 0) {
            float t = 0.f;
            #pragma unroll
            for (int j = 0; j < 8; j++) t += red[j];
            bc = t;
        }
        __syncthreads();
        rr[mat] = e / bc;
        float* dst = mat == 0 ? S1o : S2o;
        dst[((size_t)b*HW + i)*HW + tid] = rr[mat];
        __syncthreads();
    }
    g_S12[((size_t)b*HW + i)*HW + tid] = to_tf32(rr[0] + rr[1]);
}

// ---------------- K34: fused M = S12 @ C2view, then out = C2 + lrelu(Wo.M+b) ---
// Block tile: ALL 256 GEMM rows x 64 cols. grid (CW/64=256, 1, NB), 256 thr.
// Phase 1: GEMM over k (8 warps, warp tile 32x64), acc -> ms[c][pix] in smem.
// Phase 2: conv 64(o) x 256(pix) x 64(c) via 1-pass tf32 MMA + residual.
// smem (dynamic 67584B): As[256][36] (36864B) | Bs[32][72] (at 36864, 9216B);
//   ms[64][264] (67584B) aliases the whole region after the GEMM loop.
__global__ __launch_bounds__(256) void k34_fused(float* __restrict__ out) {
    extern __shared__ char sm_raw[];
    float* As = (float*)sm_raw;                 // [256][36]
    float* Bs = (float*)(sm_raw + 36864);       // [32][72]
    float* ms = (float*)sm_raw;                 // [64][264]
    int b = blockIdx.z;
    int n0 = blockIdx.x * 64;
    const float* Ag = g_S12 + (size_t)b * HW * HW;
    const float* Bg = g_C2 + (size_t)b * NC * NP;
    int tid = threadIdx.x;
    int lane = tid & 31;
    int warp = tid >> 5;                         // 0..7: GEMM m rows warp*32..+31
    int g = lane >> 2, tig = lane & 3;

    float acc[2][8][4];
    #pragma unroll
    for (int mf = 0; mf < 2; mf++)
        #pragma unroll
        for (int nf = 0; nf < 8; nf++)
            #pragma unroll
            for (int r = 0; r < 4; r++) acc[mf][nf][r] = 0.f;

    for (int k0 = 0; k0 < HW; k0 += 32) {
        // A tile 256x32 f32 = 2048 float4, 8 per thread
        #pragma unroll
        for (int t = 0; t < 8; t++) {
            int idx = tid + t*256;               // 0..2047
            int row = idx >> 3, q = idx & 7;     // row 0..255, q 0..7
            *(float4*)&As[row*36 + q*4] = *(const float4*)&Ag[(size_t)row*HW + k0 + q*4];
        }
        // B tile 32x64 f32 = 512 float4, 2 per thread; tf32-round here
        #pragma unroll
        for (int t = 0; t < 2; t++) {
            int idx = tid + t*256;               // 0..511
            int row = idx >> 4, q = idx & 15;    // row 0..31, q 0..15
            float4 v = *(const float4*)&Bg[(size_t)(k0+row)*CW + n0 + q*4];
            v.x = to_tf32(v.x); v.y = to_tf32(v.y);
            v.z = to_tf32(v.z); v.w = to_tf32(v.w);
            *(float4*)&Bs[row*72 + q*4] = v;
        }
        __syncthreads();

        #pragma unroll
        for (int kk = 0; kk < 32; kk += 8) {
            uint32_t a[2][4];
            #pragma unroll
            for (int mf = 0; mf < 2; mf++) {
                int r = warp*32 + mf*16 + g;
                a[mf][0] = __float_as_uint(As[r*36 + kk + tig]);
                a[mf][1] = __float_as_uint(As[(r+8)*36 + kk + tig]);
                a[mf][2] = __float_as_uint(As[r*36 + kk + tig + 4]);
                a[mf][3] = __float_as_uint(As[(r+8)*36 + kk + tig + 4]);
            }
            #pragma unroll
            for (int nf = 0; nf < 8; nf++) {
                int c = nf*8 + g;
                uint32_t b0 = __float_as_uint(Bs[(kk + tig)*72 + c]);
                uint32_t b1 = __float_as_uint(Bs[(kk + tig + 4)*72 + c]);
                #pragma unroll
                for (int mf = 0; mf < 2; mf++)
                    mma_tf32(acc[mf][nf], a[mf][0], a[mf][1], a[mf][2], a[mf][3], b0, b1);
            }
        }
        __syncthreads();
    }

    // Stage accumulators to smem in conv layout: GEMM row m -> (c = m>>2, hh = m&3),
    // ms[c][hh*64 + w_local]. (ms aliases As/Bs; safe after the loop's final sync.)
    #pragma unroll
    for (int mf = 0; mf < 2; mf++) {
        #pragma unroll
        for (int nf = 0; nf < 8; nf++) {
            int row0 = warp*32 + mf*16 + g;
            int row1 = row0 + 8;
            int col  = nf*8 + tig*2;
            int c0 = row0 >> 2, hh0 = row0 & 3;
            int c1 = row1 >> 2, hh1 = row1 & 3;
            *(float2*)&ms[c0*264 + hh0*64 + col] = *(float2*)&acc[mf][nf][0];
            *(float2*)&ms[c1*264 + hh1*64 + col] = *(float2*)&acc[mf][nf][2];
        }
    }
    __syncthreads();

    // Conv phase: 8 warps as 4(m: o) x 2(n: pix), warp tile 16x64, 2 pix halves.
    int wm = warp >> 1;            // 0..3 -> o base wm*16
    int wn = warp & 1;             // 0..1
    int r0 = wm*16 + g;
    int o0 = r0, o1 = r0 + 8;
    float bo0 = g_bOf[o0], bo1 = g_bOf[o1];
    size_t bofs = (size_t)b * NC * NP;

    #pragma unroll
    for (int ph = 0; ph < 2; ph++) {
        int pix_base = ph*128 + wn*64;
        float acc2[8][4];
        #pragma unroll
        for (int nf = 0; nf < 8; nf++)
            #pragma unroll
            for (int r = 0; r < 4; r++) acc2[nf][r] = 0.f;

        #pragma unroll
        for (int kk = 0; kk < NC; kk += 8) {
            uint32_t a0 = __float_as_uint(g_wOt[r0*NC + kk + tig]);
            uint32_t a1 = __float_as_uint(g_wOt[(r0+8)*NC + kk + tig]);
            uint32_t a2 = __float_as_uint(g_wOt[r0*NC + kk + tig + 4]);
            uint32_t a3 = __float_as_uint(g_wOt[(r0+8)*NC + kk + tig + 4]);
            #pragma unroll
            for (int nf = 0; nf < 8; nf++) {
                int pc = pix_base + nf*8 + g;
                uint32_t b0 = __float_as_uint(to_tf32(ms[(kk + tig)*264 + pc]));
                uint32_t b1 = __float_as_uint(to_tf32(ms[(kk + tig + 4)*264 + pc]));
                mma_tf32(acc2[nf], a0, a1, a2, a3, b0, b1);
            }
        }

        #pragma unroll
        for (int nf = 0; nf < 8; nf++) {
            int pix = pix_base + nf*8 + tig*2;
            int hh = pix >> 6, wl = pix & 63;
            size_t off0 = bofs + (size_t)(o0*4 + hh)*CW + n0 + wl;
            size_t off1 = bofs + (size_t)(o1*4 + hh)*CW + n0 + wl;
            float2 c20 = *(const float2*)&g_C2[off0];
            float2 c21 = *(const float2*)&g_C2[off1];
            float2 v0, v1;
            v0.x = c20.x + lrelu(acc2[nf][0] + bo0);
            v0.y = c20.y + lrelu(acc2[nf][1] + bo0);
            v1.x = c21.x + lrelu(acc2[nf][2] + bo1);
            v1.y = c21.y + lrelu(acc2[nf][3] + bo1);
            *(float2*)&out[off0] = v0;
            *(float2*)&out[off1] = v1;
        }
    }
}

#define K34_SMEM 67584

// ---------------- launch --------------------------------------------------------
extern "C" void kernel_launch(void* const* d_in, const int* in_sizes, int n_in,
                              void* d_out, int out_size) {
    const float* x   = (const float*)d_in[0];
    const float* w1  = (const float*)d_in[1];
    const float* b1  = (const float*)d_in[2];
    const float* g1  = (const float*)d_in[3];
    const float* be1 = (const float*)d_in[4];
    const float* m1  = (const float*)d_in[5];
    const float* v1  = (const float*)d_in[6];
    const float* wA  = (const float*)d_in[7];
    const float* bA  = (const float*)d_in[8];
    const float* gA  = (const float*)d_in[9];
    const float* beA = (const float*)d_in[10];
    const float* mA  = (const float*)d_in[11];
    const float* vA  = (const float*)d_in[12];
    const float* wO  = (const float*)d_in[13];
    const float* bO  = (const float*)d_in[14];
    const float* gO  = (const float*)d_in[15];
    const float* beO = (const float*)d_in[16];
    const float* mO  = (const float*)d_in[17];
    const float* vO  = (const float*)d_in[18];

    float* out = (float*)d_out;
    float* S1o = out + (size_t)C2ELEMS;
    float* S2o = S1o + (size_t)SELEMS;

    cudaFuncSetAttribute(k34_fused, cudaFuncAttributeMaxDynamicSharedMemorySize, K34_SMEM);

    k0_fold<<<1, 64>>>(w1,b1,g1,be1,m1,v1, wA,bA,gA,beA,mA,vA, wO,bO,gO,beO,mO,vO);
    k1_c1c2<<<dim3(NP/128, NB), 256>>>(x);
    k2a_gram<<<dim3(4, 4, 2*NB), 256>>>();
    k2b_softmax<<<dim3(HW, NB), 256>>>(S1o, S2o);
    k34_fused<<<dim3(CW/64, 1, NB), 256, K34_SMEM>>>(out);
}

// round 8
// speedup vs baseline: 2.6120x; 1.0997x over previous
#include <cuda_runtime.h>
#include <cuda_bf16.h>
#include <cstdint>

// Problem constants: B=8, C=64, H=W=256
#define NB 8
#define NC 64
#define NP 65536              // H*W
#define HW 256                // H (== W)
#define CW 16384              // C*W
#define C2ELEMS (NB*NC*NP)    // 33554432
#define SELEMS  (NB*HW*HW)    // 524288
#define EPSBN 1e-5f
#define SLOPE 0.2f

// ---------------- scratch (device globals; no allocation allowed) -------------
__device__ float g_w1f[NC];
__device__ float g_b1f;
__device__ float g_wAt[NC*NC];    // [o][c], tf32-rounded, BN-folded
__device__ float g_bAf[NC];
__device__ float g_wOt[NC*NC];    // [o][c], tf32-rounded, BN-folded
__device__ float g_bOf[NC];
__device__ float g_C1[NB*NP];                 // (B,H,W)  2MB
__device__ float g_C2[C2ELEMS];               // (B,C,H,W) fp32 (GEMM src + residual)
__device__ float g_G[2*NB*HW*HW];             // gram matrices, 4MB
__device__ float g_S12[SELEMS];               // S1+S2, tf32-rounded, 2MB

__device__ __forceinline__ float lrelu(float y) { return y >= 0.f ? y : SLOPE * y; }

__device__ __forceinline__ float to_tf32(float x) {
    uint32_t r;
    asm("cvt.rna.tf32.f32 %0, %1;" : "=r"(r) : "f"(x));
    return __uint_as_float(r);
}

__device__ __forceinline__ void mma_tf32(float acc[4],
                                         uint32_t a0, uint32_t a1, uint32_t a2, uint32_t a3,
                                         uint32_t b0, uint32_t b1) {
    asm volatile(
        "mma.sync.aligned.m16n8k8.row.col.f32.tf32.tf32.f32 "
        "{%0,%1,%2,%3}, {%4,%5,%6,%7}, {%8,%9}, {%0,%1,%2,%3};"
        : "+f"(acc[0]), "+f"(acc[1]), "+f"(acc[2]), "+f"(acc[3])
        : "r"(a0), "r"(a1), "r"(a2), "r"(a3), "r"(b0), "r"(b1));
}

__device__ __forceinline__ void cp_async16(void* smem_dst, const void* gsrc) {
    uint32_t s = (uint32_t)__cvta_generic_to_shared(smem_dst);
    asm volatile("cp.async.cg.shared.global [%0], [%1], 16;" :: "r"(s), "l"(gsrc));
}

// ---------------- K0: fold BN into conv weights; tf32-round -------------------
__global__ void k0_fold(const float* __restrict__ w1, const float* __restrict__ b1,
                        const float* __restrict__ g1, const float* __restrict__ be1,
                        const float* __restrict__ m1, const float* __restrict__ v1,
                        const float* __restrict__ wA, const float* __restrict__ bA,
                        const float* __restrict__ gA, const float* __restrict__ beA,
                        const float* __restrict__ mA, const float* __restrict__ vA,
                        const float* __restrict__ wO, const float* __restrict__ bO,
                        const float* __restrict__ gO, const float* __restrict__ beO,
                        const float* __restrict__ mO, const float* __restrict__ vO) {
    int o = threadIdx.x;  // 0..63
    float aA = gA[o] * rsqrtf(vA[o] + EPSBN);
    float aO = gO[o] * rsqrtf(vO[o] + EPSBN);
    for (int c = 0; c < NC; c++) {
        g_wAt[o*NC + c] = to_tf32(aA * wA[o*NC + c]);
        g_wOt[o*NC + c] = to_tf32(aO * wO[o*NC + c]);
    }
    g_bAf[o] = aA * (bA[o] - mA[o]) + beA[o];
    g_bOf[o] = aO * (bO[o] - mO[o]) + beO[o];
    float a1 = g1[0] * rsqrtf(v1[0] + EPSBN);
    g_w1f[o] = a1 * w1[o];
    if (o == 0) g_b1f = a1 * (b1[0] - m1[0]) + be1[0];
}

// ---------------- K1: fused C1 (fp32) + C2 conv via 1-pass TF32 MMA -----------
// grid (NP/128, NB), 256 threads (8 warps: 4m x 2n, warp tile 16(o) x 64(p)).
__global__ __launch_bounds__(256) void k1_c1c2(const float* __restrict__ x) {
    __shared__ float xs[NC][136];   // [c][p]
    int b = blockIdx.y;
    int p0 = blockIdx.x * 128;
    int tid = threadIdx.x;

    const float* xb = x + (size_t)b * NC * NP;
    // 64x128 fp32 tile = 2048 float4, 8 per thread
    #pragma unroll
    for (int t = 0; t < 8; t++) {
        int i = tid + t*256;            // 0..2047
        int c = i >> 5, pq = i & 31;
        *(float4*)&xs[c][pq*4] = *(const float4*)(xb + (size_t)c*NP + p0 + pq*4);
    }
    __syncthreads();

    // C1 exact fp32 (feeds softmax outputs)
    if (tid < 128) {
        float s = 0.f;
        #pragma unroll
        for (int c = 0; c < NC; c++) s += g_w1f[c] * xs[c][tid];
        s += g_b1f;
        g_C1[(size_t)b*NP + p0 + tid] = lrelu(s);
    }

    int lane = tid & 31, warp = tid >> 5;
    int wm = warp >> 1;
    int wn = warp & 1;
    int g = lane >> 2, tig = lane & 3;
    int r0 = wm*16 + g;

    float acc[8][4];
    #pragma unroll
    for (int nf = 0; nf < 8; nf++)
        #pragma unroll
        for (int r = 0; r < 4; r++) acc[nf][r] = 0.f;

    #pragma unroll
    for (int kk = 0; kk < NC; kk += 8) {
        uint32_t a0 = __float_as_uint(g_wAt[r0*NC + kk + tig]);
        uint32_t a1 = __float_as_uint(g_wAt[(r0+8)*NC + kk + tig]);
        uint32_t a2 = __float_as_uint(g_wAt[r0*NC + kk + tig + 4]);
        uint32_t a3 = __float_as_uint(g_wAt[(r0+8)*NC + kk + tig + 4]);
        #pragma unroll
        for (int nf = 0; nf < 8; nf++) {
            int c0 = wn*64 + nf*8 + g;
            uint32_t b0 = __float_as_uint(to_tf32(xs[kk + tig][c0]));
            uint32_t b1 = __float_as_uint(to_tf32(xs[kk + tig + 4][c0]));
            mma_tf32(acc[nf], a0, a1, a2, a3, b0, b1);
        }
    }

    int o0 = wm*16 + g, o1 = o0 + 8;
    float bo0 = g_bAf[o0], bo1 = g_bAf[o1];
    #pragma unroll
    for (int nf = 0; nf < 8; nf++) {
        int col = p0 + wn*64 + nf*8 + tig*2;
        float2 v0, v1;
        v0.x = lrelu(acc[nf][0] + bo0); v0.y = lrelu(acc[nf][1] + bo0);
        v1.x = lrelu(acc[nf][2] + bo1); v1.y = lrelu(acc[nf][3] + bo1);
        *(float2*)&g_C2[(size_t)b*NC*NP + (size_t)o0*NP + col] = v0;
        *(float2*)&g_C2[(size_t)b*NC*NP + (size_t)o1*NP + col] = v1;
    }
}

// ---------------- K2a: Gram matrices G1 = C1 C1^T, G2 = C1^T C1 ---------------
__global__ __launch_bounds__(256) void k2a_gram() {
    int mat = blockIdx.z & 1;
    int b = blockIdx.z >> 1;
    int j0 = blockIdx.x * 64;
    int i0 = blockIdx.y * 64;
    __shared__ float As[32][64];
    __shared__ float Bs[32][64];
    const float* A = g_C1 + (size_t)b * NP;
    int tid = threadIdx.x;
    int ti = tid >> 4, tj = tid & 15;
    float acc[4][4];
    #pragma unroll
    for (int r = 0; r < 4; r++)
        #pragma unroll
        for (int c = 0; c < 4; c++) acc[r][c] = 0.f;

    for (int k0 = 0; k0 < HW; k0 += 32) {
        if (mat == 0) {
            int i = tid >> 2;
            int kq = (tid & 3) * 8;
            float4 va0 = *(const float4*)&A[(i0+i)*HW + k0 + kq];
            float4 va1 = *(const float4*)&A[(i0+i)*HW + k0 + kq + 4];
            As[kq+0][i]=va0.x; As[kq+1][i]=va0.y; As[kq+2][i]=va0.z; As[kq+3][i]=va0.w;
            As[kq+4][i]=va1.x; As[kq+5][i]=va1.y; As[kq+6][i]=va1.z; As[kq+7][i]=va1.w;
            float4 vb0 = *(const float4*)&A[(j0+i)*HW + k0 + kq];
            float4 vb1 = *(const float4*)&A[(j0+i)*HW + k0 + kq + 4];
            Bs[kq+0][i]=vb0.x; Bs[kq+1][i]=vb0.y; Bs[kq+2][i]=vb0.z; Bs[kq+3][i]=vb0.w;
            Bs[kq+4][i]=vb1.x; Bs[kq+5][i]=vb1.y; Bs[kq+6][i]=vb1.z; Bs[kq+7][i]=vb1.w;
        } else {
            int k = tid >> 3, iq = (tid & 7) * 8;
            *(float4*)&As[k][iq]   = *(const float4*)&A[(k0+k)*HW + i0 + iq];
            *(float4*)&As[k][iq+4] = *(const float4*)&A[(k0+k)*HW + i0 + iq + 4];
            *(float4*)&Bs[k][iq]   = *(const float4*)&A[(k0+k)*HW + j0 + iq];
            *(float4*)&Bs[k][iq+4] = *(const float4*)&A[(k0+k)*HW + j0 + iq + 4];
        }
        __syncthreads();
        #pragma unroll
        for (int kk = 0; kk < 32; kk++) {
            float4 a4 = *(float4*)&As[kk][ti*4];
            float4 b4 = *(float4*)&Bs[kk][tj*4];
            float av[4] = {a4.x,a4.y,a4.z,a4.w};
            float bv[4] = {b4.x,b4.y,b4.z,b4.w};
            #pragma unroll
            for (int r = 0; r < 4; r++)
                #pragma unroll
                for (int c = 0; c < 4; c++) acc[r][c] = fmaf(av[r], bv[c], acc[r][c]);
        }
        __syncthreads();
    }
    float* G = g_G + ((size_t)(mat*NB + b)) * HW * HW;
    #pragma unroll
    for (int r = 0; r < 4; r++) {
        float4 v; v.x=acc[r][0]; v.y=acc[r][1]; v.z=acc[r][2]; v.w=acc[r][3];
        *(float4*)&G[(i0 + ti*4 + r)*HW + j0 + tj*4] = v;
    }
}

// ---------------- K2b: row softmax -> S1,S2 (outputs), S12 (tf32-rounded) -----
__global__ __launch_bounds__(256) void k2b_softmax(float* __restrict__ S1o,
                                                   float* __restrict__ S2o) {
    int i = blockIdx.x, b = blockIdx.y, tid = threadIdx.x;
    __shared__ float red[8];
    __shared__ float bc;
    float rr[2];
    #pragma unroll
    for (int mat = 0; mat < 2; mat++) {
        float v = g_G[(((size_t)(mat*NB + b))*HW + i)*HW + tid];
        float m = v;
        #pragma unroll
        for (int o = 16; o; o >>= 1) m = fmaxf(m, __shfl_xor_sync(0xffffffffu, m, o));
        if ((tid & 31) == 0) red[tid >> 5] = m;
        __syncthreads();
        if (tid == 0) {
            float t = red[0];
            #pragma unroll
            for (int j = 1; j < 8; j++) t = fmaxf(t, red[j]);
            bc = t;
        }
        __syncthreads();
        float e = expf(v - bc);
        float s = e;
        #pragma unroll
        for (int o = 16; o; o >>= 1) s += __shfl_xor_sync(0xffffffffu, s, o);
        if ((tid & 31) == 0) red[tid >> 5] = s;
        __syncthreads();
        if (tid == 0) {
            float t = 0.f;
            #pragma unroll
            for (int j = 0; j < 8; j++) t += red[j];
            bc = t;
        }
        __syncthreads();
        rr[mat] = e / bc;
        float* dst = mat == 0 ? S1o : S2o;
        dst[((size_t)b*HW + i)*HW + tid] = rr[mat];
        __syncthreads();
    }
    g_S12[((size_t)b*HW + i)*HW + tid] = to_tf32(rr[0] + rr[1]);
}

// ---------------- K34: fused M = S12 @ C2view, then out = C2 + lrelu(Wo.M+b) ---
// Block tile: ALL 256 GEMM rows x 64 cols. grid (CW/64=256, 1, NB), 256 thr.
// GEMM k-loop is cp.async double-buffered: stage = As[256][36] + Bs[32][72]
//   (11520 floats = 46080 B), two stages = 92160 B dynamic smem.
// Conv staging ms[64][264] (67584 B) aliases the ring after the loop drains.
__global__ __launch_bounds__(256) void k34_fused(float* __restrict__ out) {
    extern __shared__ char sm_raw[];
    float* sm = (float*)sm_raw;
    float* ms = sm;                              // [64][264]
    const int STG = 11520;                       // floats per stage
    int b = blockIdx.z;
    int n0 = blockIdx.x * 64;
    const float* Ag = g_S12 + (size_t)b * HW * HW;
    const float* Bg = g_C2 + (size_t)b * NC * NP;
    int tid = threadIdx.x;
    int lane = tid & 31;
    int warp = tid >> 5;                         // 0..7: GEMM m rows warp*32..+31
    int g = lane >> 2, tig = lane & 3;

    // per-thread loader indices (fixed across iterations)
    int arow[8], aq[8];
    #pragma unroll
    for (int t = 0; t < 8; t++) { int idx = tid + t*256; arow[t] = idx >> 3; aq[t] = (idx & 7) * 4; }
    int brow[2], bq[2];
    #pragma unroll
    for (int t = 0; t < 2; t++) { int idx = tid + t*256; brow[t] = idx >> 4; bq[t] = (idx & 15) * 4; }

    // prologue: stage 0 <- k0 = 0
    {
        float* Ad = sm;            // stage 0 A
        float* Bd = sm + 9216;     // stage 0 B
        #pragma unroll
        for (int t = 0; t < 8; t++)
            cp_async16(&Ad[arow[t]*36 + aq[t]], &Ag[(size_t)arow[t]*HW + aq[t]]);
        #pragma unroll
        for (int t = 0; t < 2; t++)
            cp_async16(&Bd[brow[t]*72 + bq[t]], &Bg[(size_t)brow[t]*CW + n0 + bq[t]]);
        asm volatile("cp.async.commit_group;");
    }

    float acc[2][8][4];
    #pragma unroll
    for (int mf = 0; mf < 2; mf++)
        #pragma unroll
        for (int nf = 0; nf < 8; nf++)
            #pragma unroll
            for (int r = 0; r < 4; r++) acc[mf][nf][r] = 0.f;

    for (int k0 = 0; k0 < HW; k0 += 32) {
        int stg = (k0 >> 5) & 1;
        if (k0 + 32 < HW) {
            float* Ad = sm + (stg^1)*STG;
            float* Bd = Ad + 9216;
            int kn = k0 + 32;
            #pragma unroll
            for (int t = 0; t < 8; t++)
                cp_async16(&Ad[arow[t]*36 + aq[t]], &Ag[(size_t)arow[t]*HW + kn + aq[t]]);
            #pragma unroll
            for (int t = 0; t < 2; t++)
                cp_async16(&Bd[brow[t]*72 + bq[t]], &Bg[(size_t)(kn+brow[t])*CW + n0 + bq[t]]);
            asm volatile("cp.async.commit_group;");
            asm volatile("cp.async.wait_group 1;");
        } else {
            asm volatile("cp.async.wait_group 0;");
        }
        __syncthreads();

        const float* As = sm + stg*STG;
        const float* Bs = As + 9216;

        #pragma unroll
        for (int kk = 0; kk < 32; kk += 8) {
            uint32_t a[2][4];
            #pragma unroll
            for (int mf = 0; mf < 2; mf++) {
                int r = warp*32 + mf*16 + g;
                a[mf][0] = __float_as_uint(As[r*36 + kk + tig]);
                a[mf][1] = __float_as_uint(As[(r+8)*36 + kk + tig]);
                a[mf][2] = __float_as_uint(As[r*36 + kk + tig + 4]);
                a[mf][3] = __float_as_uint(As[(r+8)*36 + kk + tig + 4]);
            }
            #pragma unroll
            for (int nf = 0; nf < 8; nf++) {
                int c = nf*8 + g;
                uint32_t b0 = __float_as_uint(to_tf32(Bs[(kk + tig)*72 + c]));
                uint32_t b1 = __float_as_uint(to_tf32(Bs[(kk + tig + 4)*72 + c]));
                #pragma unroll
                for (int mf = 0; mf < 2; mf++)
                    mma_tf32(acc[mf][nf], a[mf][0], a[mf][1], a[mf][2], a[mf][3], b0, b1);
            }
        }
        __syncthreads();
    }

    // Stage accumulators to smem in conv layout: GEMM row m -> (c = m>>2, hh = m&3)
    #pragma unroll
    for (int mf = 0; mf < 2; mf++) {
        #pragma unroll
        for (int nf = 0; nf < 8; nf++) {
            int row0 = warp*32 + mf*16 + g;
            int row1 = row0 + 8;
            int col  = nf*8 + tig*2;
            int c0 = row0 >> 2, hh0 = row0 & 3;
            int c1 = row1 >> 2, hh1 = row1 & 3;
            *(float2*)&ms[c0*264 + hh0*64 + col] = *(float2*)&acc[mf][nf][0];
            *(float2*)&ms[c1*264 + hh1*64 + col] = *(float2*)&acc[mf][nf][2];
        }
    }
    __syncthreads();

    // Conv phase: 8 warps as 4(m: o) x 2(n: pix), warp tile 16x64, 2 pix halves.
    int wm = warp >> 1;
    int wn = warp & 1;
    int r0 = wm*16 + g;
    int o0 = r0, o1 = r0 + 8;
    float bo0 = g_bOf[o0], bo1 = g_bOf[o1];
    size_t bofs = (size_t)b * NC * NP;

    #pragma unroll
    for (int ph = 0; ph < 2; ph++) {
        int pix_base = ph*128 + wn*64;
        float acc2[8][4];
        #pragma unroll
        for (int nf = 0; nf < 8; nf++)
            #pragma unroll
            for (int r = 0; r < 4; r++) acc2[nf][r] = 0.f;

        #pragma unroll
        for (int kk = 0; kk < NC; kk += 8) {
            uint32_t a0 = __float_as_uint(g_wOt[r0*NC + kk + tig]);
            uint32_t a1 = __float_as_uint(g_wOt[(r0+8)*NC + kk + tig]);
            uint32_t a2 = __float_as_uint(g_wOt[r0*NC + kk + tig + 4]);
            uint32_t a3 = __float_as_uint(g_wOt[(r0+8)*NC + kk + tig + 4]);
            #pragma unroll
            for (int nf = 0; nf < 8; nf++) {
                int pc = pix_base + nf*8 + g;
                uint32_t b0 = __float_as_uint(to_tf32(ms[(kk + tig)*264 + pc]));
                uint32_t b1 = __float_as_uint(to_tf32(ms[(kk + tig + 4)*264 + pc]));
                mma_tf32(acc2[nf], a0, a1, a2, a3, b0, b1);
            }
        }

        #pragma unroll
        for (int nf = 0; nf < 8; nf++) {
            int pix = pix_base + nf*8 + tig*2;
            int hh = pix >> 6, wl = pix & 63;
            size_t off0 = bofs + (size_t)(o0*4 + hh)*CW + n0 + wl;
            size_t off1 = bofs + (size_t)(o1*4 + hh)*CW + n0 + wl;
            float2 c20 = *(const float2*)&g_C2[off0];
            float2 c21 = *(const float2*)&g_C2[off1];
            float2 v0, v1;
            v0.x = c20.x + lrelu(acc2[nf][0] + bo0);
            v0.y = c20.y + lrelu(acc2[nf][1] + bo0);
            v1.x = c21.x + lrelu(acc2[nf][2] + bo1);
            v1.y = c21.y + lrelu(acc2[nf][3] + bo1);
            *(float2*)&out[off0] = v0;
            *(float2*)&out[off1] = v1;
        }
    }
}

#define K34_SMEM 92160

// ---------------- launch --------------------------------------------------------
extern "C" void kernel_launch(void* const* d_in, const int* in_sizes, int n_in,
                              void* d_out, int out_size) {
    const float* x   = (const float*)d_in[0];
    const float* w1  = (const float*)d_in[1];
    const float* b1  = (const float*)d_in[2];
    const float* g1  = (const float*)d_in[3];
    const float* be1 = (const float*)d_in[4];
    const float* m1  = (const float*)d_in[5];
    const float* v1  = (const float*)d_in[6];
    const float* wA  = (const float*)d_in[7];
    const float* bA  = (const float*)d_in[8];
    const float* gA  = (const float*)d_in[9];
    const float* beA = (const float*)d_in[10];
    const float* mA  = (const float*)d_in[11];
    const float* vA  = (const float*)d_in[12];
    const float* wO  = (const float*)d_in[13];
    const float* bO  = (const float*)d_in[14];
    const float* gO  = (const float*)d_in[15];
    const float* beO = (const float*)d_in[16];
    const float* mO  = (const float*)d_in[17];
    const float* vO  = (const float*)d_in[18];

    float* out = (float*)d_out;
    float* S1o = out + (size_t)C2ELEMS;
    float* S2o = S1o + (size_t)SELEMS;

    cudaFuncSetAttribute(k34_fused, cudaFuncAttributeMaxDynamicSharedMemorySize, K34_SMEM);

    k0_fold<<<1, 64>>>(w1,b1,g1,be1,m1,v1, wA,bA,gA,beA,mA,vA, wO,bO,gO,beO,mO,vO);
    k1_c1c2<<<dim3(NP/128, NB), 256>>>(x);
    k2a_gram<<<dim3(4, 4, 2*NB), 256>>>();
    k2b_softmax<<<dim3(HW, NB), 256>>>(S1o, S2o);
    k34_fused<<<dim3(CW/64, 1, NB), 256, K34_SMEM>>>(out);
}

// round 9
// speedup vs baseline: 2.7622x; 1.0575x over previous
#include <cuda_runtime.h>
#include <cuda_fp16.h>
#include <cstdint>

// Problem constants: B=8, C=64, H=W=256
#define NB 8
#define NC 64
#define NP 65536              // H*W
#define HW 256                // H (== W)
#define CW 16384              // C*W
#define C2ELEMS (NB*NC*NP)    // 33554432
#define SELEMS  (NB*HW*HW)    // 524288
#define EPSBN 1e-5f
#define SLOPE 0.2f

// ---------------- scratch (device globals; no allocation allowed) -------------
__device__ float g_w1f[NC];
__device__ float g_b1f;
__device__ float g_wAt[NC*NC];    // [o][c], tf32-rounded, BN-folded
__device__ float g_bAf[NC];
__device__ float g_wOt[NC*NC];    // [o][c], tf32-rounded, BN-folded
__device__ float g_bOf[NC];
__device__ float g_C1[NB*NP];                 // (B,H,W)  2MB
__device__ float g_C2[C2ELEMS];               // (B,C,H,W) fp32 (residual)
__device__ __half g_C2h[C2ELEMS];             // fp16 copy for k34 GEMM B
__device__ float g_G[2*NB*HW*HW];             // gram matrices, 4MB
__device__ __half g_S12h[SELEMS];             // S1+S2 in fp16 (k34 GEMM A), 1MB

__device__ __forceinline__ float lrelu(float y) { return y >= 0.f ? y : SLOPE * y; }

__device__ __forceinline__ float to_tf32(float x) {
    uint32_t r;
    asm("cvt.rna.tf32.f32 %0, %1;" : "=r"(r) : "f"(x));
    return __uint_as_float(r);
}

__device__ __forceinline__ void mma_tf32(float acc[4],
                                         uint32_t a0, uint32_t a1, uint32_t a2, uint32_t a3,
                                         uint32_t b0, uint32_t b1) {
    asm volatile(
        "mma.sync.aligned.m16n8k8.row.col.f32.tf32.tf32.f32 "
        "{%0,%1,%2,%3}, {%4,%5,%6,%7}, {%8,%9}, {%0,%1,%2,%3};"
        : "+f"(acc[0]), "+f"(acc[1]), "+f"(acc[2]), "+f"(acc[3])
        : "r"(a0), "r"(a1), "r"(a2), "r"(a3), "r"(b0), "r"(b1));
}

__device__ __forceinline__ void mma_f16(float acc[4],
                                        uint32_t a0, uint32_t a1, uint32_t a2, uint32_t a3,
                                        uint32_t b0, uint32_t b1) {
    asm volatile(
        "mma.sync.aligned.m16n8k16.row.col.f32.f16.f16.f32 "
        "{%0,%1,%2,%3}, {%4,%5,%6,%7}, {%8,%9}, {%0,%1,%2,%3};"
        : "+f"(acc[0]), "+f"(acc[1]), "+f"(acc[2]), "+f"(acc[3])
        : "r"(a0), "r"(a1), "r"(a2), "r"(a3), "r"(b0), "r"(b1));
}

__device__ __forceinline__ void cp_async16(void* smem_dst, const void* gsrc) {
    uint32_t s = (uint32_t)__cvta_generic_to_shared(smem_dst);
    asm volatile("cp.async.cg.shared.global [%0], [%1], 16;" :: "r"(s), "l"(gsrc));
}

// ---------------- K0: fold BN into conv weights; tf32-round -------------------
__global__ void k0_fold(const float* __restrict__ w1, const float* __restrict__ b1,
                        const float* __restrict__ g1, const float* __restrict__ be1,
                        const float* __restrict__ m1, const float* __restrict__ v1,
                        const float* __restrict__ wA, const float* __restrict__ bA,
                        const float* __restrict__ gA, const float* __restrict__ beA,
                        const float* __restrict__ mA, const float* __restrict__ vA,
                        const float* __restrict__ wO, const float* __restrict__ bO,
                        const float* __restrict__ gO, const float* __restrict__ beO,
                        const float* __restrict__ mO, const float* __restrict__ vO) {
    int o = threadIdx.x;  // 0..63
    float aA = gA[o] * rsqrtf(vA[o] + EPSBN);
    float aO = gO[o] * rsqrtf(vO[o] + EPSBN);
    for (int c = 0; c < NC; c++) {
        g_wAt[o*NC + c] = to_tf32(aA * wA[o*NC + c]);
        g_wOt[o*NC + c] = to_tf32(aO * wO[o*NC + c]);
    }
    g_bAf[o] = aA * (bA[o] - mA[o]) + beA[o];
    g_bOf[o] = aO * (bO[o] - mO[o]) + beO[o];
    float a1 = g1[0] * rsqrtf(v1[0] + EPSBN);
    g_w1f[o] = a1 * w1[o];
    if (o == 0) g_b1f = a1 * (b1[0] - m1[0]) + be1[0];
}

// ---------------- K1: fused C1 (fp32) + C2 conv via 1-pass TF32 MMA -----------
// Also emits fp16 copy of C2 for the k34 GEMM.
__global__ __launch_bounds__(256) void k1_c1c2(const float* __restrict__ x) {
    __shared__ float xs[NC][136];   // [c][p]
    int b = blockIdx.y;
    int p0 = blockIdx.x * 128;
    int tid = threadIdx.x;

    const float* xb = x + (size_t)b * NC * NP;
    #pragma unroll
    for (int t = 0; t < 8; t++) {
        int i = tid + t*256;            // 0..2047
        int c = i >> 5, pq = i & 31;
        *(float4*)&xs[c][pq*4] = *(const float4*)(xb + (size_t)c*NP + p0 + pq*4);
    }
    __syncthreads();

    // C1 exact fp32 (feeds softmax outputs)
    if (tid < 128) {
        float s = 0.f;
        #pragma unroll
        for (int c = 0; c < NC; c++) s += g_w1f[c] * xs[c][tid];
        s += g_b1f;
        g_C1[(size_t)b*NP + p0 + tid] = lrelu(s);
    }

    int lane = tid & 31, warp = tid >> 5;
    int wm = warp >> 1;
    int wn = warp & 1;
    int g = lane >> 2, tig = lane & 3;
    int r0 = wm*16 + g;

    float acc[8][4];
    #pragma unroll
    for (int nf = 0; nf < 8; nf++)
        #pragma unroll
        for (int r = 0; r < 4; r++) acc[nf][r] = 0.f;

    #pragma unroll
    for (int kk = 0; kk < NC; kk += 8) {
        uint32_t a0 = __float_as_uint(g_wAt[r0*NC + kk + tig]);
        uint32_t a1 = __float_as_uint(g_wAt[(r0+8)*NC + kk + tig]);
        uint32_t a2 = __float_as_uint(g_wAt[r0*NC + kk + tig + 4]);
        uint32_t a3 = __float_as_uint(g_wAt[(r0+8)*NC + kk + tig + 4]);
        #pragma unroll
        for (int nf = 0; nf < 8; nf++) {
            int c0 = wn*64 + nf*8 + g;
            uint32_t b0 = __float_as_uint(to_tf32(xs[kk + tig][c0]));
            uint32_t b1 = __float_as_uint(to_tf32(xs[kk + tig + 4][c0]));
            mma_tf32(acc[nf], a0, a1, a2, a3, b0, b1);
        }
    }

    int o0 = wm*16 + g, o1 = o0 + 8;
    float bo0 = g_bAf[o0], bo1 = g_bAf[o1];
    #pragma unroll
    for (int nf = 0; nf < 8; nf++) {
        int col = p0 + wn*64 + nf*8 + tig*2;
        float2 v0, v1;
        v0.x = lrelu(acc[nf][0] + bo0); v0.y = lrelu(acc[nf][1] + bo0);
        v1.x = lrelu(acc[nf][2] + bo1); v1.y = lrelu(acc[nf][3] + bo1);
        size_t off0 = (size_t)b*NC*NP + (size_t)o0*NP + col;
        size_t off1 = (size_t)b*NC*NP + (size_t)o1*NP + col;
        *(float2*)&g_C2[off0] = v0;
        *(float2*)&g_C2[off1] = v1;
        *(__half2*)&g_C2h[off0] = __floats2half2_rn(v0.x, v0.y);
        *(__half2*)&g_C2h[off1] = __floats2half2_rn(v1.x, v1.y);
    }
}

// ---------------- K2a: Gram matrices G1 = C1 C1^T, G2 = C1^T C1 ---------------
__global__ __launch_bounds__(256) void k2a_gram() {
    int mat = blockIdx.z & 1;
    int b = blockIdx.z >> 1;
    int j0 = blockIdx.x * 64;
    int i0 = blockIdx.y * 64;
    __shared__ float As[32][64];
    __shared__ float Bs[32][64];
    const float* A = g_C1 + (size_t)b * NP;
    int tid = threadIdx.x;
    int ti = tid >> 4, tj = tid & 15;
    float acc[4][4];
    #pragma unroll
    for (int r = 0; r < 4; r++)
        #pragma unroll
        for (int c = 0; c < 4; c++) acc[r][c] = 0.f;

    for (int k0 = 0; k0 < HW; k0 += 32) {
        if (mat == 0) {
            int i = tid >> 2;
            int kq = (tid & 3) * 8;
            float4 va0 = *(const float4*)&A[(i0+i)*HW + k0 + kq];
            float4 va1 = *(const float4*)&A[(i0+i)*HW + k0 + kq + 4];
            As[kq+0][i]=va0.x; As[kq+1][i]=va0.y; As[kq+2][i]=va0.z; As[kq+3][i]=va0.w;
            As[kq+4][i]=va1.x; As[kq+5][i]=va1.y; As[kq+6][i]=va1.z; As[kq+7][i]=va1.w;
            float4 vb0 = *(const float4*)&A[(j0+i)*HW + k0 + kq];
            float4 vb1 = *(const float4*)&A[(j0+i)*HW + k0 + kq + 4];
            Bs[kq+0][i]=vb0.x; Bs[kq+1][i]=vb0.y; Bs[kq+2][i]=vb0.z; Bs[kq+3][i]=vb0.w;
            Bs[kq+4][i]=vb1.x; Bs[kq+5][i]=vb1.y; Bs[kq+6][i]=vb1.z; Bs[kq+7][i]=vb1.w;
        } else {
            int k = tid >> 3, iq = (tid & 7) * 8;
            *(float4*)&As[k][iq]   = *(const float4*)&A[(k0+k)*HW + i0 + iq];
            *(float4*)&As[k][iq+4] = *(const float4*)&A[(k0+k)*HW + i0 + iq + 4];
            *(float4*)&Bs[k][iq]   = *(const float4*)&A[(k0+k)*HW + j0 + iq];
            *(float4*)&Bs[k][iq+4] = *(const float4*)&A[(k0+k)*HW + j0 + iq + 4];
        }
        __syncthreads();
        #pragma unroll
        for (int kk = 0; kk < 32; kk++) {
            float4 a4 = *(float4*)&As[kk][ti*4];
            float4 b4 = *(float4*)&Bs[kk][tj*4];
            float av[4] = {a4.x,a4.y,a4.z,a4.w};
            float bv[4] = {b4.x,b4.y,b4.z,b4.w};
            #pragma unroll
            for (int r = 0; r < 4; r++)
                #pragma unroll
                for (int c = 0; c < 4; c++) acc[r][c] = fmaf(av[r], bv[c], acc[r][c]);
        }
        __syncthreads();
    }
    float* G = g_G + ((size_t)(mat*NB + b)) * HW * HW;
    #pragma unroll
    for (int r = 0; r < 4; r++) {
        float4 v; v.x=acc[r][0]; v.y=acc[r][1]; v.z=acc[r][2]; v.w=acc[r][3];
        *(float4*)&G[(i0 + ti*4 + r)*HW + j0 + tj*4] = v;
    }
}

// ---------------- K2b: row softmax -> S1,S2 (outputs), S12 (fp16) -------------
__global__ __launch_bounds__(256) void k2b_softmax(float* __restrict__ S1o,
                                                   float* __restrict__ S2o) {
    int i = blockIdx.x, b = blockIdx.y, tid = threadIdx.x;
    __shared__ float red[8];
    __shared__ float bc;
    float rr[2];
    #pragma unroll
    for (int mat = 0; mat < 2; mat++) {
        float v = g_G[(((size_t)(mat*NB + b))*HW + i)*HW + tid];
        float m = v;
        #pragma unroll
        for (int o = 16; o; o >>= 1) m = fmaxf(m, __shfl_xor_sync(0xffffffffu, m, o));
        if ((tid & 31) == 0) red[tid >> 5] = m;
        __syncthreads();
        if (tid == 0) {
            float t = red[0];
            #pragma unroll
            for (int j = 1; j < 8; j++) t = fmaxf(t, red[j]);
            bc = t;
        }
        __syncthreads();
        float e = expf(v - bc);
        float s = e;
        #pragma unroll
        for (int o = 16; o; o >>= 1) s += __shfl_xor_sync(0xffffffffu, s, o);
        if ((tid & 31) == 0) red[tid >> 5] = s;
        __syncthreads();
        if (tid == 0) {
            float t = 0.f;
            #pragma unroll
            for (int j = 0; j < 8; j++) t += red[j];
            bc = t;
        }
        __syncthreads();
        rr[mat] = e / bc;
        float* dst = mat == 0 ? S1o : S2o;
        dst[((size_t)b*HW + i)*HW + tid] = rr[mat];
        __syncthreads();
    }
    g_S12h[((size_t)b*HW + i)*HW + tid] = __float2half_rn(rr[0] + rr[1]);
}

// ---------------- K34: fused M = S12 @ C2view (fp16 HMMA), conv + residual ----
// Block: all 256 GEMM rows x 64 cols. grid (256, 1, NB), 256 thr (8 warps, 32m each).
// fp16 double-buffered ring: stage = As[256][40] + Bs[32][72] halves
//   = 12544 halves = 25088 B; two stages = 50176 B.
// Conv staging ms[64][264] fp32 (67584 B) aliases ring after drain. smem = 67584.
__global__ __launch_bounds__(256) void k34_fused(float* __restrict__ out) {
    extern __shared__ char sm_raw[];
    __half* ring = (__half*)sm_raw;
    float* ms = (float*)sm_raw;                  // [64][264]
    const int STG = 12544;                       // halves per stage
    int b = blockIdx.z;
    int n0 = blockIdx.x * 64;
    const __half* Ag = g_S12h + (size_t)b * HW * HW;
    const __half* Bg = g_C2h + (size_t)b * NC * NP;
    int tid = threadIdx.x;
    int lane = tid & 31;
    int warp = tid >> 5;                         // GEMM m rows warp*32..+31
    int g = lane >> 2, tig = lane & 3;

    // loader indices: A 256x32 halves = 1024 16B-chunks (4/thread); B 32x64 = 256 (1/thread)
    int arow[4], aq[4];
    #pragma unroll
    for (int t = 0; t < 4; t++) { int idx = tid + t*256; arow[t] = idx >> 2; aq[t] = (idx & 3) * 8; }
    int brow = tid >> 3, bq = (tid & 7) * 8;

    // ldmatrix lane address components
    int a_row = warp*32 + (lane & 15);           // + mf*16
    int a_col8 = (lane >> 4) * 8;                // + kf*16
    int b_row = ((lane >> 3) & 1) * 8 + (lane & 7);  // + kf*16
    int b_col8 = (lane >> 4) * 8;                // + nb*16

    // prologue: stage 0 <- k0 = 0
    {
        __half* Ad = ring;
        __half* Bd = ring + 10240;
        #pragma unroll
        for (int t = 0; t < 4; t++)
            cp_async16(&Ad[arow[t]*40 + aq[t]], &Ag[(size_t)arow[t]*HW + aq[t]]);
        cp_async16(&Bd[brow*72 + bq], &Bg[(size_t)brow*CW + n0 + bq]);
        asm volatile("cp.async.commit_group;");
    }

    float acc[2][8][4];
    #pragma unroll
    for (int mf = 0; mf < 2; mf++)
        #pragma unroll
        for (int nf = 0; nf < 8; nf++)
            #pragma unroll
            for (int r = 0; r < 4; r++) acc[mf][nf][r] = 0.f;

    for (int k0 = 0; k0 < HW; k0 += 32) {
        int stg = (k0 >> 5) & 1;
        if (k0 + 32 < HW) {
            __half* Ad = ring + (stg^1)*STG;
            __half* Bd = Ad + 10240;
            int kn = k0 + 32;
            #pragma unroll
            for (int t = 0; t < 4; t++)
                cp_async16(&Ad[arow[t]*40 + aq[t]], &Ag[(size_t)arow[t]*HW + kn + aq[t]]);
            cp_async16(&Bd[brow*72 + bq], &Bg[(size_t)(kn+brow)*CW + n0 + bq]);
            asm volatile("cp.async.commit_group;");
            asm volatile("cp.async.wait_group 1;");
        } else {
            asm volatile("cp.async.wait_group 0;");
        }
        __syncthreads();

        const __half* As = ring + stg*STG;
        const __half* Bs = As + 10240;

        #pragma unroll
        for (int kf = 0; kf < 2; kf++) {
            uint32_t a[2][4];
            #pragma unroll
            for (int mf = 0; mf < 2; mf++) {
                const __half* p = &As[(a_row + mf*16)*40 + kf*16 + a_col8];
                uint32_t ad = (uint32_t)__cvta_generic_to_shared(p);
                asm volatile("ldmatrix.sync.aligned.m8n8.x4.shared.b16 {%0,%1,%2,%3}, [%4];"
                    : "=r"(a[mf][0]), "=r"(a[mf][1]), "=r"(a[mf][2]), "=r"(a[mf][3])
                    : "r"(ad));
            }
            #pragma unroll
            for (int nb = 0; nb < 4; nb++) {
                uint32_t bb[4];
                const __half* p = &Bs[(kf*16 + b_row)*72 + nb*16 + b_col8];
                uint32_t ad = (uint32_t)__cvta_generic_to_shared(p);
                asm volatile("ldmatrix.sync.aligned.m8n8.x4.trans.shared.b16 {%0,%1,%2,%3}, [%4];"
                    : "=r"(bb[0]), "=r"(bb[1]), "=r"(bb[2]), "=r"(bb[3])
                    : "r"(ad));
                #pragma unroll
                for (int mf = 0; mf < 2; mf++) {
                    mma_f16(acc[mf][nb*2],   a[mf][0], a[mf][1], a[mf][2], a[mf][3], bb[0], bb[1]);
                    mma_f16(acc[mf][nb*2+1], a[mf][0], a[mf][1], a[mf][2], a[mf][3], bb[2], bb[3]);
                }
            }
        }
        __syncthreads();
    }

    // Stage accumulators to smem in conv layout: GEMM row m -> (c = m>>2, hh = m&3)
    #pragma unroll
    for (int mf = 0; mf < 2; mf++) {
        #pragma unroll
        for (int nf = 0; nf < 8; nf++) {
            int row0 = warp*32 + mf*16 + g;
            int row1 = row0 + 8;
            int col  = nf*8 + tig*2;
            int c0 = row0 >> 2, hh0 = row0 & 3;
            int c1 = row1 >> 2, hh1 = row1 & 3;
            *(float2*)&ms[c0*264 + hh0*64 + col] = *(float2*)&acc[mf][nf][0];
            *(float2*)&ms[c1*264 + hh1*64 + col] = *(float2*)&acc[mf][nf][2];
        }
    }
    __syncthreads();

    // Conv phase: 8 warps as 4(m: o) x 2(n: pix), warp tile 16x64, 2 pix halves.
    int wm = warp >> 1;
    int wn = warp & 1;
    int r0 = wm*16 + g;
    int o0 = r0, o1 = r0 + 8;
    float bo0 = g_bOf[o0], bo1 = g_bOf[o1];
    size_t bofs = (size_t)b * NC * NP;

    #pragma unroll
    for (int ph = 0; ph < 2; ph++) {
        int pix_base = ph*128 + wn*64;
        float acc2[8][4];
        #pragma unroll
        for (int nf = 0; nf < 8; nf++)
            #pragma unroll
            for (int r = 0; r < 4; r++) acc2[nf][r] = 0.f;

        #pragma unroll
        for (int kk = 0; kk < NC; kk += 8) {
            uint32_t a0 = __float_as_uint(g_wOt[r0*NC + kk + tig]);
            uint32_t a1 = __float_as_uint(g_wOt[(r0+8)*NC + kk + tig]);
            uint32_t a2 = __float_as_uint(g_wOt[r0*NC + kk + tig + 4]);
            uint32_t a3 = __float_as_uint(g_wOt[(r0+8)*NC + kk + tig + 4]);
            #pragma unroll
            for (int nf = 0; nf < 8; nf++) {
                int pc = pix_base + nf*8 + g;
                uint32_t b0 = __float_as_uint(to_tf32(ms[(kk + tig)*264 + pc]));
                uint32_t b1 = __float_as_uint(to_tf32(ms[(kk + tig + 4)*264 + pc]));
                mma_tf32(acc2[nf], a0, a1, a2, a3, b0, b1);
            }
        }

        #pragma unroll
        for (int nf = 0; nf < 8; nf++) {
            int pix = pix_base + nf*8 + tig*2;
            int hh = pix >> 6, wl = pix & 63;
            size_t off0 = bofs + (size_t)(o0*4 + hh)*CW + n0 + wl;
            size_t off1 = bofs + (size_t)(o1*4 + hh)*CW + n0 + wl;
            float2 c20 = *(const float2*)&g_C2[off0];
            float2 c21 = *(const float2*)&g_C2[off1];
            float2 v0, v1;
            v0.x = c20.x + lrelu(acc2[nf][0] + bo0);
            v0.y = c20.y + lrelu(acc2[nf][1] + bo0);
            v1.x = c21.x + lrelu(acc2[nf][2] + bo1);
            v1.y = c21.y + lrelu(acc2[nf][3] + bo1);
            *(float2*)&out[off0] = v0;
            *(float2*)&out[off1] = v1;
        }
    }
}

#define K34_SMEM 67584

// ---------------- launch --------------------------------------------------------
extern "C" void kernel_launch(void* const* d_in, const int* in_sizes, int n_in,
                              void* d_out, int out_size) {
    const float* x   = (const float*)d_in[0];
    const float* w1  = (const float*)d_in[1];
    const float* b1  = (const float*)d_in[2];
    const float* g1  = (const float*)d_in[3];
    const float* be1 = (const float*)d_in[4];
    const float* m1  = (const float*)d_in[5];
    const float* v1  = (const float*)d_in[6];
    const float* wA  = (const float*)d_in[7];
    const float* bA  = (const float*)d_in[8];
    const float* gA  = (const float*)d_in[9];
    const float* beA = (const float*)d_in[10];
    const float* mA  = (const float*)d_in[11];
    const float* vA  = (const float*)d_in[12];
    const float* wO  = (const float*)d_in[13];
    const float* bO  = (const float*)d_in[14];
    const float* gO  = (const float*)d_in[15];
    const float* beO = (const float*)d_in[16];
    const float* mO  = (const float*)d_in[17];
    const float* vO  = (const float*)d_in[18];

    float* out = (float*)d_out;
    float* S1o = out + (size_t)C2ELEMS;
    float* S2o = S1o + (size_t)SELEMS;

    cudaFuncSetAttribute(k34_fused, cudaFuncAttributeMaxDynamicSharedMemorySize, K34_SMEM);

    k0_fold<<<1, 64>>>(w1,b1,g1,be1,m1,v1, wA,bA,gA,beA,mA,vA, wO,bO,gO,beO,mO,vO);
    k1_c1c2<<<dim3(NP/128, NB), 256>>>(x);
    k2a_gram<<<dim3(4, 4, 2*NB), 256>>>();
    k2b_softmax<<<dim3(HW, NB), 256>>>(S1o, S2o);
    k34_fused<<<dim3(CW/64, 1, NB), 256, K34_SMEM>>>(out);
}

// round 10
// speedup vs baseline: 3.0631x; 1.1089x over previous
#include <cuda_runtime.h>
#include <cuda_fp16.h>
#include <cstdint>

// Problem constants: B=8, C=64, H=W=256
#define NB 8
#define NC 64
#define NP 65536              // H*W
#define HW 256                // H (== W)
#define CW 16384              // C*W
#define C2ELEMS (NB*NC*NP)    // 33554432
#define SELEMS  (NB*HW*HW)    // 524288
#define EPSBN 1e-5f
#define SLOPE 0.2f

// ---------------- scratch (device globals; no allocation allowed) -------------
__device__ float g_w1f[NC];
__device__ float g_b1f;
__device__ float g_wAt[NC*NC];    // [o][c], tf32-rounded, BN-folded
__device__ float g_bAf[NC];
__device__ float g_wOt[NC*NC];    // [o][c], tf32-rounded, BN-folded
__device__ float g_bOf[NC];
__device__ float g_C1[NB*NP];                 // (B,H,W)  2MB
__device__ __half g_C2h[C2ELEMS];             // fp16 C2 (GEMM B + residual), 67MB
__device__ float g_G[2*NB*HW*HW];             // gram matrices, 4MB
__device__ __half g_S12h[SELEMS];             // S1+S2 in fp16 (k34 GEMM A), 1MB

__device__ __forceinline__ float lrelu(float y) { return y >= 0.f ? y : SLOPE * y; }

__device__ __forceinline__ float to_tf32(float x) {
    uint32_t r;
    asm("cvt.rna.tf32.f32 %0, %1;" : "=r"(r) : "f"(x));
    return __uint_as_float(r);
}

__device__ __forceinline__ void mma_tf32(float acc[4],
                                         uint32_t a0, uint32_t a1, uint32_t a2, uint32_t a3,
                                         uint32_t b0, uint32_t b1) {
    asm volatile(
        "mma.sync.aligned.m16n8k8.row.col.f32.tf32.tf32.f32 "
        "{%0,%1,%2,%3}, {%4,%5,%6,%7}, {%8,%9}, {%0,%1,%2,%3};"
        : "+f"(acc[0]), "+f"(acc[1]), "+f"(acc[2]), "+f"(acc[3])
        : "r"(a0), "r"(a1), "r"(a2), "r"(a3), "r"(b0), "r"(b1));
}

__device__ __forceinline__ void mma_f16(float acc[4],
                                        uint32_t a0, uint32_t a1, uint32_t a2, uint32_t a3,
                                        uint32_t b0, uint32_t b1) {
    asm volatile(
        "mma.sync.aligned.m16n8k16.row.col.f32.f16.f16.f32 "
        "{%0,%1,%2,%3}, {%4,%5,%6,%7}, {%8,%9}, {%0,%1,%2,%3};"
        : "+f"(acc[0]), "+f"(acc[1]), "+f"(acc[2]), "+f"(acc[3])
        : "r"(a0), "r"(a1), "r"(a2), "r"(a3), "r"(b0), "r"(b1));
}

__device__ __forceinline__ void cp_async16(void* smem_dst, const void* gsrc) {
    uint32_t s = (uint32_t)__cvta_generic_to_shared(smem_dst);
    asm volatile("cp.async.cg.shared.global [%0], [%1], 16;" :: "r"(s), "l"(gsrc));
}

// ---------------- K0: fold BN into conv weights; tf32-round -------------------
__global__ void k0_fold(const float* __restrict__ w1, const float* __restrict__ b1,
                        const float* __restrict__ g1, const float* __restrict__ be1,
                        const float* __restrict__ m1, const float* __restrict__ v1,
                        const float* __restrict__ wA, const float* __restrict__ bA,
                        const float* __restrict__ gA, const float* __restrict__ beA,
                        const float* __restrict__ mA, const float* __restrict__ vA,
                        const float* __restrict__ wO, const float* __restrict__ bO,
                        const float* __restrict__ gO, const float* __restrict__ beO,
                        const float* __restrict__ mO, const float* __restrict__ vO) {
    int o = threadIdx.x;  // 0..63
    float aA = gA[o] * rsqrtf(vA[o] + EPSBN);
    float aO = gO[o] * rsqrtf(vO[o] + EPSBN);
    for (int c = 0; c < NC; c++) {
        g_wAt[o*NC + c] = to_tf32(aA * wA[o*NC + c]);
        g_wOt[o*NC + c] = to_tf32(aO * wO[o*NC + c]);
    }
    g_bAf[o] = aA * (bA[o] - mA[o]) + beA[o];
    g_bOf[o] = aO * (bO[o] - mO[o]) + beO[o];
    float a1 = g1[0] * rsqrtf(v1[0] + EPSBN);
    g_w1f[o] = a1 * w1[o];
    if (o == 0) g_b1f = a1 * (b1[0] - m1[0]) + be1[0];
}

// ---------------- K1: fused C1 (fp32) + C2 conv via 1-pass TF32 MMA -----------
// Emits ONLY fp16 C2 (GEMM B operand and residual source).
__global__ __launch_bounds__(256) void k1_c1c2(const float* __restrict__ x) {
    __shared__ float xs[NC][136];   // [c][p]
    int b = blockIdx.y;
    int p0 = blockIdx.x * 128;
    int tid = threadIdx.x;

    const float* xb = x + (size_t)b * NC * NP;
    #pragma unroll
    for (int t = 0; t < 8; t++) {
        int i = tid + t*256;            // 0..2047
        int c = i >> 5, pq = i & 31;
        *(float4*)&xs[c][pq*4] = *(const float4*)(xb + (size_t)c*NP + p0 + pq*4);
    }
    __syncthreads();

    // C1 exact fp32 (feeds softmax outputs)
    if (tid < 128) {
        float s = 0.f;
        #pragma unroll
        for (int c = 0; c < NC; c++) s += g_w1f[c] * xs[c][tid];
        s += g_b1f;
        g_C1[(size_t)b*NP + p0 + tid] = lrelu(s);
    }

    int lane = tid & 31, warp = tid >> 5;
    int wm = warp >> 1;
    int wn = warp & 1;
    int g = lane >> 2, tig = lane & 3;
    int r0 = wm*16 + g;

    float acc[8][4];
    #pragma unroll
    for (int nf = 0; nf < 8; nf++)
        #pragma unroll
        for (int r = 0; r < 4; r++) acc[nf][r] = 0.f;

    #pragma unroll
    for (int kk = 0; kk < NC; kk += 8) {
        uint32_t a0 = __float_as_uint(g_wAt[r0*NC + kk + tig]);
        uint32_t a1 = __float_as_uint(g_wAt[(r0+8)*NC + kk + tig]);
        uint32_t a2 = __float_as_uint(g_wAt[r0*NC + kk + tig + 4]);
        uint32_t a3 = __float_as_uint(g_wAt[(r0+8)*NC + kk + tig + 4]);
        #pragma unroll
        for (int nf = 0; nf < 8; nf++) {
            int c0 = wn*64 + nf*8 + g;
            uint32_t b0 = __float_as_uint(to_tf32(xs[kk + tig][c0]));
            uint32_t b1 = __float_as_uint(to_tf32(xs[kk + tig + 4][c0]));
            mma_tf32(acc[nf], a0, a1, a2, a3, b0, b1);
        }
    }

    int o0 = wm*16 + g, o1 = o0 + 8;
    float bo0 = g_bAf[o0], bo1 = g_bAf[o1];
    #pragma unroll
    for (int nf = 0; nf < 8; nf++) {
        int col = p0 + wn*64 + nf*8 + tig*2;
        size_t off0 = (size_t)b*NC*NP + (size_t)o0*NP + col;
        size_t off1 = (size_t)b*NC*NP + (size_t)o1*NP + col;
        *(__half2*)&g_C2h[off0] = __floats2half2_rn(lrelu(acc[nf][0] + bo0),
                                                    lrelu(acc[nf][1] + bo0));
        *(__half2*)&g_C2h[off1] = __floats2half2_rn(lrelu(acc[nf][2] + bo1),
                                                    lrelu(acc[nf][3] + bo1));
    }
}

// ---------------- K2a: Gram matrices G1 = C1 C1^T, G2 = C1^T C1 ---------------
__global__ __launch_bounds__(256) void k2a_gram() {
    int mat = blockIdx.z & 1;
    int b = blockIdx.z >> 1;
    int j0 = blockIdx.x * 64;
    int i0 = blockIdx.y * 64;
    __shared__ float As[32][64];
    __shared__ float Bs[32][64];
    const float* A = g_C1 + (size_t)b * NP;
    int tid = threadIdx.x;
    int ti = tid >> 4, tj = tid & 15;
    float acc[4][4];
    #pragma unroll
    for (int r = 0; r < 4; r++)
        #pragma unroll
        for (int c = 0; c < 4; c++) acc[r][c] = 0.f;

    for (int k0 = 0; k0 < HW; k0 += 32) {
        if (mat == 0) {
            int i = tid >> 2;
            int kq = (tid & 3) * 8;
            float4 va0 = *(const float4*)&A[(i0+i)*HW + k0 + kq];
            float4 va1 = *(const float4*)&A[(i0+i)*HW + k0 + kq + 4];
            As[kq+0][i]=va0.x; As[kq+1][i]=va0.y; As[kq+2][i]=va0.z; As[kq+3][i]=va0.w;
            As[kq+4][i]=va1.x; As[kq+5][i]=va1.y; As[kq+6][i]=va1.z; As[kq+7][i]=va1.w;
            float4 vb0 = *(const float4*)&A[(j0+i)*HW + k0 + kq];
            float4 vb1 = *(const float4*)&A[(j0+i)*HW + k0 + kq + 4];
            Bs[kq+0][i]=vb0.x; Bs[kq+1][i]=vb0.y; Bs[kq+2][i]=vb0.z; Bs[kq+3][i]=vb0.w;
            Bs[kq+4][i]=vb1.x; Bs[kq+5][i]=vb1.y; Bs[kq+6][i]=vb1.z; Bs[kq+7][i]=vb1.w;
        } else {
            int k = tid >> 3, iq = (tid & 7) * 8;
            *(float4*)&As[k][iq]   = *(const float4*)&A[(k0+k)*HW + i0 + iq];
            *(float4*)&As[k][iq+4] = *(const float4*)&A[(k0+k)*HW + i0 + iq + 4];
            *(float4*)&Bs[k][iq]   = *(const float4*)&A[(k0+k)*HW + j0 + iq];
            *(float4*)&Bs[k][iq+4] = *(const float4*)&A[(k0+k)*HW + j0 + iq + 4];
        }
        __syncthreads();
        #pragma unroll
        for (int kk = 0; kk < 32; kk++) {
            float4 a4 = *(float4*)&As[kk][ti*4];
            float4 b4 = *(float4*)&Bs[kk][tj*4];
            float av[4] = {a4.x,a4.y,a4.z,a4.w};
            float bv[4] = {b4.x,b4.y,b4.z,b4.w};
            #pragma unroll
            for (int r = 0; r < 4; r++)
                #pragma unroll
                for (int c = 0; c < 4; c++) acc[r][c] = fmaf(av[r], bv[c], acc[r][c]);
        }
        __syncthreads();
    }
    float* G = g_G + ((size_t)(mat*NB + b)) * HW * HW;
    #pragma unroll
    for (int r = 0; r < 4; r++) {
        float4 v; v.x=acc[r][0]; v.y=acc[r][1]; v.z=acc[r][2]; v.w=acc[r][3];
        *(float4*)&G[(i0 + ti*4 + r)*HW + j0 + tj*4] = v;
    }
}

// ---------------- K2b: row softmax -> S1,S2 (outputs), S12 (fp16) -------------
__global__ __launch_bounds__(256) void k2b_softmax(float* __restrict__ S1o,
                                                   float* __restrict__ S2o) {
    int i = blockIdx.x, b = blockIdx.y, tid = threadIdx.x;
    __shared__ float red[8];
    __shared__ float bc;
    float rr[2];
    #pragma unroll
    for (int mat = 0; mat < 2; mat++) {
        float v = g_G[(((size_t)(mat*NB + b))*HW + i)*HW + tid];
        float m = v;
        #pragma unroll
        for (int o = 16; o; o >>= 1) m = fmaxf(m, __shfl_xor_sync(0xffffffffu, m, o));
        if ((tid & 31) == 0) red[tid >> 5] = m;
        __syncthreads();
        if (tid == 0) {
            float t = red[0];
            #pragma unroll
            for (int j = 1; j < 8; j++) t = fmaxf(t, red[j]);
            bc = t;
        }
        __syncthreads();
        float e = expf(v - bc);
        float s = e;
        #pragma unroll
        for (int o = 16; o; o >>= 1) s += __shfl_xor_sync(0xffffffffu, s, o);
        if ((tid & 31) == 0) red[tid >> 5] = s;
        __syncthreads();
        if (tid == 0) {
            float t = 0.f;
            #pragma unroll
            for (int j = 0; j < 8; j++) t += red[j];
            bc = t;
        }
        __syncthreads();
        rr[mat] = e / bc;
        float* dst = mat == 0 ? S1o : S2o;
        dst[((size_t)b*HW + i)*HW + tid] = rr[mat];
        __syncthreads();
    }
    g_S12h[((size_t)b*HW + i)*HW + tid] = __float2half_rn(rr[0] + rr[1]);
}

// ---------------- K34: fused M = S12 @ C2view (fp16 HMMA), conv + residual ----
// Block: all 256 GEMM rows x 64 cols. grid (256, 1, NB), 256 thr (8 warps, 32m each).
// fp16 double-buffered ring: stage = As[256][40] + Bs[32][72] halves = 25088 B;
// two stages = 50176 B. Conv staging ms[64][264] fp32 aliases ring. smem = 67584.
__global__ __launch_bounds__(256) void k34_fused(float* __restrict__ out) {
    extern __shared__ char sm_raw[];
    __half* ring = (__half*)sm_raw;
    float* ms = (float*)sm_raw;                  // [64][264]
    const int STG = 12544;                       // halves per stage
    int b = blockIdx.z;
    int n0 = blockIdx.x * 64;
    const __half* Ag = g_S12h + (size_t)b * HW * HW;
    const __half* Bg = g_C2h + (size_t)b * NC * NP;
    int tid = threadIdx.x;
    int lane = tid & 31;
    int warp = tid >> 5;                         // GEMM m rows warp*32..+31
    int g = lane >> 2, tig = lane & 3;

    // loader indices: A 256x32 halves = 1024 16B-chunks (4/thread); B 32x64 = 256 (1/thread)
    int arow[4], aq[4];
    #pragma unroll
    for (int t = 0; t < 4; t++) { int idx = tid + t*256; arow[t] = idx >> 2; aq[t] = (idx & 3) * 8; }
    int brow = tid >> 3, bq = (tid & 7) * 8;

    // ldmatrix lane address components
    int a_row = warp*32 + (lane & 15);           // + mf*16
    int a_col8 = (lane >> 4) * 8;                // + kf*16
    int b_row = ((lane >> 3) & 1) * 8 + (lane & 7);  // + kf*16
    int b_col8 = (lane >> 4) * 8;                // + nb*16

    // prologue: stage 0 <- k0 = 0
    {
        __half* Ad = ring;
        __half* Bd = ring + 10240;
        #pragma unroll
        for (int t = 0; t < 4; t++)
            cp_async16(&Ad[arow[t]*40 + aq[t]], &Ag[(size_t)arow[t]*HW + aq[t]]);
        cp_async16(&Bd[brow*72 + bq], &Bg[(size_t)brow*CW + n0 + bq]);
        asm volatile("cp.async.commit_group;");
    }

    float acc[2][8][4];
    #pragma unroll
    for (int mf = 0; mf < 2; mf++)
        #pragma unroll
        for (int nf = 0; nf < 8; nf++)
            #pragma unroll
            for (int r = 0; r < 4; r++) acc[mf][nf][r] = 0.f;

    for (int k0 = 0; k0 < HW; k0 += 32) {
        int stg = (k0 >> 5) & 1;
        if (k0 + 32 < HW) {
            __half* Ad = ring + (stg^1)*STG;
            __half* Bd = Ad + 10240;
            int kn = k0 + 32;
            #pragma unroll
            for (int t = 0; t < 4; t++)
                cp_async16(&Ad[arow[t]*40 + aq[t]], &Ag[(size_t)arow[t]*HW + kn + aq[t]]);
            cp_async16(&Bd[brow*72 + bq], &Bg[(size_t)(kn+brow)*CW + n0 + bq]);
            asm volatile("cp.async.commit_group;");
            asm volatile("cp.async.wait_group 1;");
        } else {
            asm volatile("cp.async.wait_group 0;");
        }
        __syncthreads();

        const __half* As = ring + stg*STG;
        const __half* Bs = As + 10240;

        #pragma unroll
        for (int kf = 0; kf < 2; kf++) {
            uint32_t a[2][4];
            #pragma unroll
            for (int mf = 0; mf < 2; mf++) {
                const __half* p = &As[(a_row + mf*16)*40 + kf*16 + a_col8];
                uint32_t ad = (uint32_t)__cvta_generic_to_shared(p);
                asm volatile("ldmatrix.sync.aligned.m8n8.x4.shared.b16 {%0,%1,%2,%3}, [%4];"
                    : "=r"(a[mf][0]), "=r"(a[mf][1]), "=r"(a[mf][2]), "=r"(a[mf][3])
                    : "r"(ad));
            }
            #pragma unroll
            for (int nb = 0; nb < 4; nb++) {
                uint32_t bb[4];
                const __half* p = &Bs[(kf*16 + b_row)*72 + nb*16 + b_col8];
                uint32_t ad = (uint32_t)__cvta_generic_to_shared(p);
                asm volatile("ldmatrix.sync.aligned.m8n8.x4.trans.shared.b16 {%0,%1,%2,%3}, [%4];"
                    : "=r"(bb[0]), "=r"(bb[1]), "=r"(bb[2]), "=r"(bb[3])
                    : "r"(ad));
                #pragma unroll
                for (int mf = 0; mf < 2; mf++) {
                    mma_f16(acc[mf][nb*2],   a[mf][0], a[mf][1], a[mf][2], a[mf][3], bb[0], bb[1]);
                    mma_f16(acc[mf][nb*2+1], a[mf][0], a[mf][1], a[mf][2], a[mf][3], bb[2], bb[3]);
                }
            }
        }
        __syncthreads();
    }

    // Stage accumulators to smem in conv layout: GEMM row m -> (c = m>>2, hh = m&3)
    #pragma unroll
    for (int mf = 0; mf < 2; mf++) {
        #pragma unroll
        for (int nf = 0; nf < 8; nf++) {
            int row0 = warp*32 + mf*16 + g;
            int row1 = row0 + 8;
            int col  = nf*8 + tig*2;
            int c0 = row0 >> 2, hh0 = row0 & 3;
            int c1 = row1 >> 2, hh1 = row1 & 3;
            *(float2*)&ms[c0*264 + hh0*64 + col] = *(float2*)&acc[mf][nf][0];
            *(float2*)&ms[c1*264 + hh1*64 + col] = *(float2*)&acc[mf][nf][2];
        }
    }
    __syncthreads();

    // Conv phase: 8 warps as 4(m: o) x 2(n: pix), warp tile 16x64, 2 pix halves.
    int wm = warp >> 1;
    int wn = warp & 1;
    int r0 = wm*16 + g;
    int o0 = r0, o1 = r0 + 8;
    float bo0 = g_bOf[o0], bo1 = g_bOf[o1];
    size_t bofs = (size_t)b * NC * NP;

    #pragma unroll
    for (int ph = 0; ph < 2; ph++) {
        int pix_base = ph*128 + wn*64;
        float acc2[8][4];
        #pragma unroll
        for (int nf = 0; nf < 8; nf++)
            #pragma unroll
            for (int r = 0; r < 4; r++) acc2[nf][r] = 0.f;

        #pragma unroll
        for (int kk = 0; kk < NC; kk += 8) {
            uint32_t a0 = __float_as_uint(g_wOt[r0*NC + kk + tig]);
            uint32_t a1 = __float_as_uint(g_wOt[(r0+8)*NC + kk + tig]);
            uint32_t a2 = __float_as_uint(g_wOt[r0*NC + kk + tig + 4]);
            uint32_t a3 = __float_as_uint(g_wOt[(r0+8)*NC + kk + tig + 4]);
            #pragma unroll
            for (int nf = 0; nf < 8; nf++) {
                int pc = pix_base + nf*8 + g;
                uint32_t b0 = __float_as_uint(to_tf32(ms[(kk + tig)*264 + pc]));
                uint32_t b1 = __float_as_uint(to_tf32(ms[(kk + tig + 4)*264 + pc]));
                mma_tf32(acc2[nf], a0, a1, a2, a3, b0, b1);
            }
        }

        #pragma unroll
        for (int nf = 0; nf < 8; nf++) {
            int pix = pix_base + nf*8 + tig*2;
            int hh = pix >> 6, wl = pix & 63;
            size_t off0 = bofs + (size_t)(o0*4 + hh)*CW + n0 + wl;
            size_t off1 = bofs + (size_t)(o1*4 + hh)*CW + n0 + wl;
            float2 c20 = __half22float2(*(const __half2*)&g_C2h[off0]);
            float2 c21 = __half22float2(*(const __half2*)&g_C2h[off1]);
            float2 v0, v1;
            v0.x = c20.x + lrelu(acc2[nf][0] + bo0);
            v0.y = c20.y + lrelu(acc2[nf][1] + bo0);
            v1.x = c21.x + lrelu(acc2[nf][2] + bo1);
            v1.y = c21.y + lrelu(acc2[nf][3] + bo1);
            *(float2*)&out[off0] = v0;
            *(float2*)&out[off1] = v1;
        }
    }
}

#define K34_SMEM 67584

// ---------------- launch --------------------------------------------------------
extern "C" void kernel_launch(void* const* d_in, const int* in_sizes, int n_in,
                              void* d_out, int out_size) {
    const float* x   = (const float*)d_in[0];
    const float* w1  = (const float*)d_in[1];
    const float* b1  = (const float*)d_in[2];
    const float* g1  = (const float*)d_in[3];
    const float* be1 = (const float*)d_in[4];
    const float* m1  = (const float*)d_in[5];
    const float* v1  = (const float*)d_in[6];
    const float* wA  = (const float*)d_in[7];
    const float* bA  = (const float*)d_in[8];
    const float* gA  = (const float*)d_in[9];
    const float* beA = (const float*)d_in[10];
    const float* mA  = (const float*)d_in[11];
    const float* vA  = (const float*)d_in[12];
    const float* wO  = (const float*)d_in[13];
    const float* bO  = (const float*)d_in[14];
    const float* gO  = (const float*)d_in[15];
    const float* beO = (const float*)d_in[16];
    const float* mO  = (const float*)d_in[17];
    const float* vO  = (const float*)d_in[18];

    float* out = (float*)d_out;
    float* S1o = out + (size_t)C2ELEMS;
    float* S2o = S1o + (size_t)SELEMS;

    cudaFuncSetAttribute(k34_fused, cudaFuncAttributeMaxDynamicSharedMemorySize, K34_SMEM);

    k0_fold<<<1, 64>>>(w1,b1,g1,be1,m1,v1, wA,bA,gA,beA,mA,vA, wO,bO,gO,beO,mO,vO);
    k1_c1c2<<<dim3(NP/128, NB), 256>>>(x);
    k2a_gram<<<dim3(4, 4, 2*NB), 256>>>();
    k2b_softmax<<<dim3(HW, NB), 256>>>(S1o, S2o);
    k34_fused<<<dim3(CW/64, 1, NB), 256, K34_SMEM>>>(out);
}

// round 11
// speedup vs baseline: 3.5898x; 1.1720x over previous
#include <cuda_runtime.h>
#include <cuda_fp16.h>
#include <cstdint>

// Problem constants: B=8, C=64, H=W=256
#define NB 8
#define NC 64
#define NP 65536              // H*W
#define HW 256                // H (== W)
#define CW 16384              // C*W
#define C2ELEMS (NB*NC*NP)    // 33554432
#define SELEMS  (NB*HW*HW)    // 524288
#define EPSBN 1e-5f
#define SLOPE 0.2f

// ---------------- scratch (device globals; no allocation allowed) -------------
__device__ float g_w1f[NC];
__device__ float g_b1f;
__device__ __half g_wAh[NC*NC];   // [o][c], fp16, BN-folded
__device__ float g_bAf[NC];
__device__ __half g_wOh[NC*NC];   // [o][c], fp16, BN-folded
__device__ float g_bOf[NC];
__device__ float g_C1[NB*NP];                 // (B,H,W)  2MB
__device__ __half g_C2h[C2ELEMS];             // fp16 C2 (GEMM B + residual), 67MB
__device__ float g_G[2*NB*HW*HW];             // gram matrices, 4MB
__device__ __half g_S12h[SELEMS];             // S1+S2 in fp16 (k34 GEMM A), 1MB

__device__ __forceinline__ float lrelu(float y) { return y >= 0.f ? y : SLOPE * y; }

__device__ __forceinline__ void mma_f16(float acc[4],
                                        uint32_t a0, uint32_t a1, uint32_t a2, uint32_t a3,
                                        uint32_t b0, uint32_t b1) {
    asm volatile(
        "mma.sync.aligned.m16n8k16.row.col.f32.f16.f16.f32 "
        "{%0,%1,%2,%3}, {%4,%5,%6,%7}, {%8,%9}, {%0,%1,%2,%3};"
        : "+f"(acc[0]), "+f"(acc[1]), "+f"(acc[2]), "+f"(acc[3])
        : "r"(a0), "r"(a1), "r"(a2), "r"(a3), "r"(b0), "r"(b1));
}

__device__ __forceinline__ void cp_async16(void* smem_dst, const void* gsrc) {
    uint32_t s = (uint32_t)__cvta_generic_to_shared(smem_dst);
    asm volatile("cp.async.cg.shared.global [%0], [%1], 16;" :: "r"(s), "l"(gsrc));
}

__device__ __forceinline__ void ldmx4(uint32_t r[4], const __half* p) {
    uint32_t ad = (uint32_t)__cvta_generic_to_shared(p);
    asm volatile("ldmatrix.sync.aligned.m8n8.x4.shared.b16 {%0,%1,%2,%3}, [%4];"
        : "=r"(r[0]), "=r"(r[1]), "=r"(r[2]), "=r"(r[3]) : "r"(ad));
}
__device__ __forceinline__ void ldmx4t(uint32_t r[4], const __half* p) {
    uint32_t ad = (uint32_t)__cvta_generic_to_shared(p);
    asm volatile("ldmatrix.sync.aligned.m8n8.x4.trans.shared.b16 {%0,%1,%2,%3}, [%4];"
        : "=r"(r[0]), "=r"(r[1]), "=r"(r[2]), "=r"(r[3]) : "r"(ad));
}

// ---------------- K0: fold BN into conv weights; fp16-round -------------------
__global__ void k0_fold(const float* __restrict__ w1, const float* __restrict__ b1,
                        const float* __restrict__ g1, const float* __restrict__ be1,
                        const float* __restrict__ m1, const float* __restrict__ v1,
                        const float* __restrict__ wA, const float* __restrict__ bA,
                        const float* __restrict__ gA, const float* __restrict__ beA,
                        const float* __restrict__ mA, const float* __restrict__ vA,
                        const float* __restrict__ wO, const float* __restrict__ bO,
                        const float* __restrict__ gO, const float* __restrict__ beO,
                        const float* __restrict__ mO, const float* __restrict__ vO) {
    int o = threadIdx.x;  // 0..63
    float aA = gA[o] * rsqrtf(vA[o] + EPSBN);
    float aO = gO[o] * rsqrtf(vO[o] + EPSBN);
    for (int c = 0; c < NC; c++) {
        g_wAh[o*NC + c] = __float2half_rn(aA * wA[o*NC + c]);
        g_wOh[o*NC + c] = __float2half_rn(aO * wO[o*NC + c]);
    }
    g_bAf[o] = aA * (bA[o] - mA[o]) + beA[o];
    g_bOf[o] = aO * (bO[o] - mO[o]) + beO[o];
    float a1 = g1[0] * rsqrtf(v1[0] + EPSBN);
    g_w1f[o] = a1 * w1[o];
    if (o == 0) g_b1f = a1 * (b1[0] - m1[0]) + be1[0];
}

// ---------------- K1: fused C1 (fp32) + C2 conv via fp16 k16 MMA --------------
// grid (NP/128, NB), 256 threads (8 warps: 4m x 2n, warp tile 16(o) x 64(p)).
// Dynamic smem: xs[64][132] f32 (33792B) + xh[64][136] fp16 (17408B) = 51200B.
__global__ __launch_bounds__(256) void k1_c1c2(const float* __restrict__ x) {
    extern __shared__ char k1sm[];
    float* xs = (float*)k1sm;                    // [64][132]
    __half* xh = (__half*)(k1sm + 33792);        // [64][136]
    int b = blockIdx.y;
    int p0 = blockIdx.x * 128;
    int tid = threadIdx.x;

    const float* xb = x + (size_t)b * NC * NP;
    #pragma unroll
    for (int t = 0; t < 8; t++) {
        int i = tid + t*256;            // 0..2047
        int c = i >> 5, pq = i & 31;
        float4 v = *(const float4*)(xb + (size_t)c*NP + p0 + pq*4);
        *(float4*)&xs[c*132 + pq*4] = v;
        uint2 h;
        __half2 h0 = __floats2half2_rn(v.x, v.y);
        __half2 h1 = __floats2half2_rn(v.z, v.w);
        h.x = *(uint32_t*)&h0; h.y = *(uint32_t*)&h1;
        *(uint2*)&xh[c*136 + pq*4] = h;
    }
    __syncthreads();

    // C1 exact fp32 (feeds softmax outputs)
    if (tid < 128) {
        float s = 0.f;
        #pragma unroll
        for (int c = 0; c < NC; c++) s += g_w1f[c] * xs[c*132 + tid];
        s += g_b1f;
        g_C1[(size_t)b*NP + p0 + tid] = lrelu(s);
    }

    int lane = tid & 31, warp = tid >> 5;
    int wm = warp >> 1;
    int wn = warp & 1;
    int g = lane >> 2, tig = lane & 3;
    int r0 = wm*16 + g;
    int b_row = ((lane >> 3) & 1) * 8 + (lane & 7);
    int b_col8 = (lane >> 4) * 8;

    float acc[8][4];
    #pragma unroll
    for (int nf = 0; nf < 8; nf++)
        #pragma unroll
        for (int r = 0; r < 4; r++) acc[nf][r] = 0.f;

    #pragma unroll
    for (int kf = 0; kf < 4; kf++) {
        int kk = kf*16;
        uint32_t a0 = *(const uint32_t*)&g_wAh[r0*NC + kk + 2*tig];
        uint32_t a1 = *(const uint32_t*)&g_wAh[(r0+8)*NC + kk + 2*tig];
        uint32_t a2 = *(const uint32_t*)&g_wAh[r0*NC + kk + 2*tig + 8];
        uint32_t a3 = *(const uint32_t*)&g_wAh[(r0+8)*NC + kk + 2*tig + 8];
        #pragma unroll
        for (int nb = 0; nb < 4; nb++) {
            uint32_t bb[4];
            ldmx4t(bb, &xh[(kk + b_row)*136 + wn*64 + nb*16 + b_col8]);
            mma_f16(acc[nb*2],   a0, a1, a2, a3, bb[0], bb[1]);
            mma_f16(acc[nb*2+1], a0, a1, a2, a3, bb[2], bb[3]);
        }
    }

    int o0 = wm*16 + g, o1 = o0 + 8;
    float bo0 = g_bAf[o0], bo1 = g_bAf[o1];
    #pragma unroll
    for (int nf = 0; nf < 8; nf++) {
        int col = p0 + wn*64 + nf*8 + tig*2;
        size_t off0 = (size_t)b*NC*NP + (size_t)o0*NP + col;
        size_t off1 = (size_t)b*NC*NP + (size_t)o1*NP + col;
        *(__half2*)&g_C2h[off0] = __floats2half2_rn(lrelu(acc[nf][0] + bo0),
                                                    lrelu(acc[nf][1] + bo0));
        *(__half2*)&g_C2h[off1] = __floats2half2_rn(lrelu(acc[nf][2] + bo1),
                                                    lrelu(acc[nf][3] + bo1));
    }
}
#define K1_SMEM 51200

// ---------------- K2a: Gram matrices G1 = C1 C1^T, G2 = C1^T C1 ---------------
__global__ __launch_bounds__(256) void k2a_gram() {
    int mat = blockIdx.z & 1;
    int b = blockIdx.z >> 1;
    int j0 = blockIdx.x * 64;
    int i0 = blockIdx.y * 64;
    __shared__ float As[32][64];
    __shared__ float Bs[32][64];
    const float* A = g_C1 + (size_t)b * NP;
    int tid = threadIdx.x;
    int ti = tid >> 4, tj = tid & 15;
    float acc[4][4];
    #pragma unroll
    for (int r = 0; r < 4; r++)
        #pragma unroll
        for (int c = 0; c < 4; c++) acc[r][c] = 0.f;

    for (int k0 = 0; k0 < HW; k0 += 32) {
        if (mat == 0) {
            int i = tid >> 2;
            int kq = (tid & 3) * 8;
            float4 va0 = *(const float4*)&A[(i0+i)*HW + k0 + kq];
            float4 va1 = *(const float4*)&A[(i0+i)*HW + k0 + kq + 4];
            As[kq+0][i]=va0.x; As[kq+1][i]=va0.y; As[kq+2][i]=va0.z; As[kq+3][i]=va0.w;
            As[kq+4][i]=va1.x; As[kq+5][i]=va1.y; As[kq+6][i]=va1.z; As[kq+7][i]=va1.w;
            float4 vb0 = *(const float4*)&A[(j0+i)*HW + k0 + kq];
            float4 vb1 = *(const float4*)&A[(j0+i)*HW + k0 + kq + 4];
            Bs[kq+0][i]=vb0.x; Bs[kq+1][i]=vb0.y; Bs[kq+2][i]=vb0.z; Bs[kq+3][i]=vb0.w;
            Bs[kq+4][i]=vb1.x; Bs[kq+5][i]=vb1.y; Bs[kq+6][i]=vb1.z; Bs[kq+7][i]=vb1.w;
        } else {
            int k = tid >> 3, iq = (tid & 7) * 8;
            *(float4*)&As[k][iq]   = *(const float4*)&A[(k0+k)*HW + i0 + iq];
            *(float4*)&As[k][iq+4] = *(const float4*)&A[(k0+k)*HW + i0 + iq + 4];
            *(float4*)&Bs[k][iq]   = *(const float4*)&A[(k0+k)*HW + j0 + iq];
            *(float4*)&Bs[k][iq+4] = *(const float4*)&A[(k0+k)*HW + j0 + iq + 4];
        }
        __syncthreads();
        #pragma unroll
        for (int kk = 0; kk < 32; kk++) {
            float4 a4 = *(float4*)&As[kk][ti*4];
            float4 b4 = *(float4*)&Bs[kk][tj*4];
            float av[4] = {a4.x,a4.y,a4.z,a4.w};
            float bv[4] = {b4.x,b4.y,b4.z,b4.w};
            #pragma unroll
            for (int r = 0; r < 4; r++)
                #pragma unroll
                for (int c = 0; c < 4; c++) acc[r][c] = fmaf(av[r], bv[c], acc[r][c]);
        }
        __syncthreads();
    }
    float* G = g_G + ((size_t)(mat*NB + b)) * HW * HW;
    #pragma unroll
    for (int r = 0; r < 4; r++) {
        float4 v; v.x=acc[r][0]; v.y=acc[r][1]; v.z=acc[r][2]; v.w=acc[r][3];
        *(float4*)&G[(i0 + ti*4 + r)*HW + j0 + tj*4] = v;
    }
}

// ---------------- K2b: row softmax -> S1,S2 (outputs), S12 (fp16) -------------
__global__ __launch_bounds__(256) void k2b_softmax(float* __restrict__ S1o,
                                                   float* __restrict__ S2o) {
    int i = blockIdx.x, b = blockIdx.y, tid = threadIdx.x;
    __shared__ float red[8];
    __shared__ float bc;
    float rr[2];
    #pragma unroll
    for (int mat = 0; mat < 2; mat++) {
        float v = g_G[(((size_t)(mat*NB + b))*HW + i)*HW + tid];
        float m = v;
        #pragma unroll
        for (int o = 16; o; o >>= 1) m = fmaxf(m, __shfl_xor_sync(0xffffffffu, m, o));
        if ((tid & 31) == 0) red[tid >> 5] = m;
        __syncthreads();
        if (tid == 0) {
            float t = red[0];
            #pragma unroll
            for (int j = 1; j < 8; j++) t = fmaxf(t, red[j]);
            bc = t;
        }
        __syncthreads();
        float e = expf(v - bc);
        float s = e;
        #pragma unroll
        for (int o = 16; o; o >>= 1) s += __shfl_xor_sync(0xffffffffu, s, o);
        if ((tid & 31) == 0) red[tid >> 5] = s;
        __syncthreads();
        if (tid == 0) {
            float t = 0.f;
            #pragma unroll
            for (int j = 0; j < 8; j++) t += red[j];
            bc = t;
        }
        __syncthreads();
        rr[mat] = e / bc;
        float* dst = mat == 0 ? S1o : S2o;
        dst[((size_t)b*HW + i)*HW + tid] = rr[mat];
        __syncthreads();
    }
    g_S12h[((size_t)b*HW + i)*HW + tid] = __float2half_rn(rr[0] + rr[1]);
}

// ---------------- K34: fused M = S12 @ C2view (fp16 HMMA), fp16 conv, residual -
// Block: all 256 GEMM rows x 64 cols. grid (256, 1, NB), 256 thr (8 warps).
// fp16 double-buffered ring: stage = As[256][40] + Bs[32][72] halves = 25088 B;
// two stages = 50176 B. Conv staging ms[64][264] fp16 (33792 B) aliases ring.
__global__ __launch_bounds__(256) void k34_fused(float* __restrict__ out) {
    extern __shared__ char sm_raw[];
    __half* ring = (__half*)sm_raw;
    __half* ms = (__half*)sm_raw;                // [64][264]
    const int STG = 12544;                       // halves per stage
    int b = blockIdx.z;
    int n0 = blockIdx.x * 64;
    const __half* Ag = g_S12h + (size_t)b * HW * HW;
    const __half* Bg = g_C2h + (size_t)b * NC * NP;
    int tid = threadIdx.x;
    int lane = tid & 31;
    int warp = tid >> 5;                         // GEMM m rows warp*32..+31
    int g = lane >> 2, tig = lane & 3;

    // loader indices: A 256x32 halves = 1024 16B-chunks (4/thread); B 32x64 = 256 (1/thread)
    int arow[4], aq[4];
    #pragma unroll
    for (int t = 0; t < 4; t++) { int idx = tid + t*256; arow[t] = idx >> 2; aq[t] = (idx & 3) * 8; }
    int brow = tid >> 3, bq = (tid & 7) * 8;

    // ldmatrix lane address components
    int a_row = warp*32 + (lane & 15);           // + mf*16
    int a_col8 = (lane >> 4) * 8;                // + kf*16
    int b_row = ((lane >> 3) & 1) * 8 + (lane & 7);  // + kf*16
    int b_col8 = (lane >> 4) * 8;                // + nb*16

    // prologue: stage 0 <- k0 = 0
    {
        __half* Ad = ring;
        __half* Bd = ring + 10240;
        #pragma unroll
        for (int t = 0; t < 4; t++)
            cp_async16(&Ad[arow[t]*40 + aq[t]], &Ag[(size_t)arow[t]*HW + aq[t]]);
        cp_async16(&Bd[brow*72 + bq], &Bg[(size_t)brow*CW + n0 + bq]);
        asm volatile("cp.async.commit_group;");
    }

    float acc[2][8][4];
    #pragma unroll
    for (int mf = 0; mf < 2; mf++)
        #pragma unroll
        for (int nf = 0; nf < 8; nf++)
            #pragma unroll
            for (int r = 0; r < 4; r++) acc[mf][nf][r] = 0.f;

    for (int k0 = 0; k0 < HW; k0 += 32) {
        int stg = (k0 >> 5) & 1;
        if (k0 + 32 < HW) {
            __half* Ad = ring + (stg^1)*STG;
            __half* Bd = Ad + 10240;
            int kn = k0 + 32;
            #pragma unroll
            for (int t = 0; t < 4; t++)
                cp_async16(&Ad[arow[t]*40 + aq[t]], &Ag[(size_t)arow[t]*HW + kn + aq[t]]);
            cp_async16(&Bd[brow*72 + bq], &Bg[(size_t)(kn+brow)*CW + n0 + bq]);
            asm volatile("cp.async.commit_group;");
            asm volatile("cp.async.wait_group 1;");
        } else {
            asm volatile("cp.async.wait_group 0;");
        }
        __syncthreads();

        const __half* As = ring + stg*STG;
        const __half* Bs = As + 10240;

        #pragma unroll
        for (int kf = 0; kf < 2; kf++) {
            uint32_t a[2][4];
            #pragma unroll
            for (int mf = 0; mf < 2; mf++)
                ldmx4(a[mf], &As[(a_row + mf*16)*40 + kf*16 + a_col8]);
            #pragma unroll
            for (int nb = 0; nb < 4; nb++) {
                uint32_t bb[4];
                ldmx4t(bb, &Bs[(kf*16 + b_row)*72 + nb*16 + b_col8]);
                #pragma unroll
                for (int mf = 0; mf < 2; mf++) {
                    mma_f16(acc[mf][nb*2],   a[mf][0], a[mf][1], a[mf][2], a[mf][3], bb[0], bb[1]);
                    mma_f16(acc[mf][nb*2+1], a[mf][0], a[mf][1], a[mf][2], a[mf][3], bb[2], bb[3]);
                }
            }
        }
        __syncthreads();
    }

    // Stage accumulators to smem (fp16) in conv layout: row m -> (c = m>>2, hh = m&3)
    #pragma unroll
    for (int mf = 0; mf < 2; mf++) {
        #pragma unroll
        for (int nf = 0; nf < 8; nf++) {
            int row0 = warp*32 + mf*16 + g;
            int row1 = row0 + 8;
            int col  = nf*8 + tig*2;
            int c0 = row0 >> 2, hh0 = row0 & 3;
            int c1 = row1 >> 2, hh1 = row1 & 3;
            *(__half2*)&ms[c0*264 + hh0*64 + col] = __floats2half2_rn(acc[mf][nf][0], acc[mf][nf][1]);
            *(__half2*)&ms[c1*264 + hh1*64 + col] = __floats2half2_rn(acc[mf][nf][2], acc[mf][nf][3]);
        }
    }
    __syncthreads();

    // Conv phase (fp16 k16): 8 warps as 4(m: o) x 2(n: pix), warp tile 16x64, 2 halves.
    int wm = warp >> 1;
    int wn = warp & 1;
    int r0 = wm*16 + g;
    int o0 = r0, o1 = r0 + 8;
    float bo0 = g_bOf[o0], bo1 = g_bOf[o1];
    size_t bofs = (size_t)b * NC * NP;

    #pragma unroll
    for (int ph = 0; ph < 2; ph++) {
        int pix_base = ph*128 + wn*64;
        float acc2[8][4];
        #pragma unroll
        for (int nf = 0; nf < 8; nf++)
            #pragma unroll
            for (int r = 0; r < 4; r++) acc2[nf][r] = 0.f;

        #pragma unroll
        for (int kf = 0; kf < 4; kf++) {
            int kk = kf*16;
            uint32_t a0 = *(const uint32_t*)&g_wOh[r0*NC + kk + 2*tig];
            uint32_t a1 = *(const uint32_t*)&g_wOh[(r0+8)*NC + kk + 2*tig];
            uint32_t a2 = *(const uint32_t*)&g_wOh[r0*NC + kk + 2*tig + 8];
            uint32_t a3 = *(const uint32_t*)&g_wOh[(r0+8)*NC + kk + 2*tig + 8];
            #pragma unroll
            for (int nb = 0; nb < 4; nb++) {
                uint32_t bb[4];
                ldmx4t(bb, &ms[(kk + b_row)*264 + pix_base + nb*16 + b_col8]);
                mma_f16(acc2[nb*2],   a0, a1, a2, a3, bb[0], bb[1]);
                mma_f16(acc2[nb*2+1], a0, a1, a2, a3, bb[2], bb[3]);
            }
        }

        #pragma unroll
        for (int nf = 0; nf < 8; nf++) {
            int pix = pix_base + nf*8 + tig*2;
            int hh = pix >> 6, wl = pix & 63;
            size_t off0 = bofs + (size_t)(o0*4 + hh)*CW + n0 + wl;
            size_t off1 = bofs + (size_t)(o1*4 + hh)*CW + n0 + wl;
            float2 c20 = __half22float2(*(const __half2*)&g_C2h[off0]);
            float2 c21 = __half22float2(*(const __half2*)&g_C2h[off1]);
            float2 v0, v1;
            v0.x = c20.x + lrelu(acc2[nf][0] + bo0);
            v0.y = c20.y + lrelu(acc2[nf][1] + bo0);
            v1.x = c21.x + lrelu(acc2[nf][2] + bo1);
            v1.y = c21.y + lrelu(acc2[nf][3] + bo1);
            *(float2*)&out[off0] = v0;
            *(float2*)&out[off1] = v1;
        }
    }
}

#define K34_SMEM 50176

// ---------------- launch --------------------------------------------------------
extern "C" void kernel_launch(void* const* d_in, const int* in_sizes, int n_in,
                              void* d_out, int out_size) {
    const float* x   = (const float*)d_in[0];
    const float* w1  = (const float*)d_in[1];
    const float* b1  = (const float*)d_in[2];
    const float* g1  = (const float*)d_in[3];
    const float* be1 = (const float*)d_in[4];
    const float* m1  = (const float*)d_in[5];
    const float* v1  = (const float*)d_in[6];
    const float* wA  = (const float*)d_in[7];
    const float* bA  = (const float*)d_in[8];
    const float* gA  = (const float*)d_in[9];
    const float* beA = (const float*)d_in[10];
    const float* mA  = (const float*)d_in[11];
    const float* vA  = (const float*)d_in[12];
    const float* wO  = (const float*)d_in[13];
    const float* bO  = (const float*)d_in[14];
    const float* gO  = (const float*)d_in[15];
    const float* beO = (const float*)d_in[16];
    const float* mO  = (const float*)d_in[17];
    const float* vO  = (const float*)d_in[18];

    float* out = (float*)d_out;
    float* S1o = out + (size_t)C2ELEMS;
    float* S2o = S1o + (size_t)SELEMS;

    cudaFuncSetAttribute(k1_c1c2, cudaFuncAttributeMaxDynamicSharedMemorySize, K1_SMEM);
    cudaFuncSetAttribute(k34_fused, cudaFuncAttributeMaxDynamicSharedMemorySize, K34_SMEM);

    k0_fold<<<1, 64>>>(w1,b1,g1,be1,m1,v1, wA,bA,gA,beA,mA,vA, wO,bO,gO,beO,mO,vO);
    k1_c1c2<<<dim3(NP/128, NB), 256, K1_SMEM>>>(x);
    k2a_gram<<<dim3(4, 4, 2*NB), 256>>>();
    k2b_softmax<<<dim3(HW, NB), 256>>>(S1o, S2o);
    k34_fused<<<dim3(CW/64, 1, NB), 256, K34_SMEM>>>(out);
}